// round 9
// baseline (speedup 1.0000x reference)
#include <cuda_runtime.h>
#include <cuda_bf16.h>
#include <cstdint>

#define B_  4
#define S_  2048
#define D_  1024
#define H_  16
#define DH_ 64
#define M_  (B_ * S_)   // 8192

// ---------------- scratch (allocation-free: device globals) ----------------
__device__ __nv_bfloat16 g_xnb  [M_ * D_];      // 16 MB, bf16 LN output
__device__ float         g_qkv  [M_ * 3 * D_];  // 96 MB fp32 (Q|K|V)
__device__ __nv_bfloat16 g_attnb[M_ * D_];      // 16 MB, bf16 attention output
__device__ __nv_bfloat16 g_wqkvb[3 * D_ * D_];  // 6 MB, bf16 [Wq;Wkv] (3072x1024 K-major)
__device__ __nv_bfloat16 g_wob  [D_ * D_];      // 2 MB, bf16 Wo

// ---------------- helpers ----------------
__device__ __forceinline__ float to_tf32(float x) {
    uint32_t u;
    asm("cvt.rna.tf32.f32 %0, %1;" : "=r"(u) : "f"(x));
    return __uint_as_float(u);
}

__device__ __forceinline__ uint32_t smem_u32(const void* p) {
    uint32_t a;
    asm("{ .reg .u64 t; cvta.to.shared.u64 t, %1; cvt.u32.u64 %0, t; }" : "=r"(a) : "l"(p));
    return a;
}

__device__ __forceinline__ void cp16(uint32_t dst, const void* src) {
    asm volatile("cp.async.cg.shared.global [%0], [%1], 16;" :: "r"(dst), "l"(src) : "memory");
}

__device__ __forceinline__ void ldsm4(uint32_t& r0, uint32_t& r1, uint32_t& r2, uint32_t& r3,
                                      uint32_t addr) {
    asm volatile("ldmatrix.sync.aligned.m8n8.x4.shared.b16 {%0,%1,%2,%3}, [%4];"
                 : "=r"(r0), "=r"(r1), "=r"(r2), "=r"(r3) : "r"(addr));
}

// D += A(16x16) * B(16x8), bf16 in / f32 accumulate
__device__ __forceinline__ void mma16(float* d, const uint32_t* a, uint32_t b0, uint32_t b1) {
    asm volatile(
        "mma.sync.aligned.m16n8k16.row.col.f32.bf16.bf16.f32 "
        "{%0,%1,%2,%3}, {%4,%5,%6,%7}, {%8,%9}, {%0,%1,%2,%3};\n"
        : "+f"(d[0]), "+f"(d[1]), "+f"(d[2]), "+f"(d[3])
        : "r"(a[0]), "r"(a[1]), "r"(a[2]), "r"(a[3]), "r"(b0), "r"(b1));
}

// legacy tf32 mma for the attention kernel (unchanged)
__device__ __forceinline__ void mma8(float* d, const float* a, const float* b) {
    asm volatile(
        "mma.sync.aligned.m16n8k8.row.col.f32.tf32.tf32.f32 "
        "{%0,%1,%2,%3}, {%4,%5,%6,%7}, {%8,%9}, {%0,%1,%2,%3};\n"
        : "+f"(d[0]), "+f"(d[1]), "+f"(d[2]), "+f"(d[3])
        : "r"(__float_as_uint(a[0])), "r"(__float_as_uint(a[1])),
          "r"(__float_as_uint(a[2])), "r"(__float_as_uint(a[3])),
          "r"(__float_as_uint(b[0])), "r"(__float_as_uint(b[1])));
}

// ---------------- kernel 1: LayerNorm (writes bf16 xn) ----------------
__global__ void __launch_bounds__(256) ln_kernel(
    const float* __restrict__ x, const float* __restrict__ gw,
    const float* __restrict__ bw, __nv_bfloat16* __restrict__ out)
{
    __shared__ float red0[8], red1[8];
    const int row = blockIdx.x;
    const int tid = threadIdx.x;
    const float4 v = ((const float4*)(x + (size_t)row * D_))[tid];

    float s  = v.x + v.y + v.z + v.w;
    float s2 = v.x*v.x + v.y*v.y + v.z*v.z + v.w*v.w;
    #pragma unroll
    for (int o = 16; o; o >>= 1) {
        s  += __shfl_xor_sync(0xffffffffu, s,  o);
        s2 += __shfl_xor_sync(0xffffffffu, s2, o);
    }
    if ((tid & 31) == 0) { red0[tid >> 5] = s; red1[tid >> 5] = s2; }
    __syncthreads();
    s = 0.f; s2 = 0.f;
    #pragma unroll
    for (int i = 0; i < 8; i++) { s += red0[i]; s2 += red1[i]; }

    const float mu  = s * (1.0f / D_);
    float var = s2 * (1.0f / D_) - mu * mu;
    if (var < 0.f) var = 0.f;
    const float r = rsqrtf(var + 1e-5f);

    const float4 g4 = ((const float4*)gw)[tid];
    const float4 b4 = ((const float4*)bw)[tid];
    const __nv_bfloat162 p0 = __floats2bfloat162_rn((v.x - mu) * r * g4.x + b4.x,
                                                    (v.y - mu) * r * g4.y + b4.y);
    const __nv_bfloat162 p1 = __floats2bfloat162_rn((v.z - mu) * r * g4.z + b4.z,
                                                    (v.w - mu) * r * g4.w + b4.w);
    uint2 pk;
    pk.x = *(const uint32_t*)&p0;
    pk.y = *(const uint32_t*)&p1;
    ((uint2*)(out + (size_t)row * D_))[tid] = pk;
}

// ---------------- kernel 1b: pack + round weights to bf16 ----------------
__global__ void __launch_bounds__(256) round_w_kernel(
    const float* __restrict__ Wq, const float* __restrict__ Wkv,
    const float* __restrict__ Wo, __nv_bfloat16* __restrict__ wqkv,
    __nv_bfloat16* __restrict__ wo)
{
    const int i = blockIdx.x * 256 + threadIdx.x;     // float4 index; grid covers 1M
    const int QKV4 = 3 * 1024 * 1024 / 4;             // 786432
    const int Q4   = 1024 * 1024 / 4;                 // 262144
    float4 v;
    __nv_bfloat16* dst;
    int j;
    if (i < QKV4) {
        v = (i < Q4) ? ((const float4*)Wq)[i] : ((const float4*)Wkv)[i - Q4];
        dst = wqkv; j = i;
    } else {
        j = i - QKV4;
        v = ((const float4*)Wo)[j];
        dst = wo;
    }
    const __nv_bfloat162 p0 = __floats2bfloat162_rn(v.x, v.y);
    const __nv_bfloat162 p1 = __floats2bfloat162_rn(v.z, v.w);
    uint2 pk;
    pk.x = *(const uint32_t*)&p0;
    pk.y = *(const uint32_t*)&p1;
    ((uint2*)dst)[j] = pk;
}

// ---------------- kernel 2/4: bf16 mma.m16n8k16 + ldmatrix GEMM ----------------
// C[m,n] = sum_k A[m,k]*W[n,k] + bias[n] (+resid[m,n]);  K = 1024 fixed.
// BM=128, BN=128, BK=32, 4-stage cp.async. 8 warps (2x4), warp tile 64x32.
#define GBM 128
#define GBN 128
#define GBK 32
#define GNT (1024 / GBK)              // 32 k-tiles
#define GROWB 80                      // padded row bytes (32 bf16 = 64B + 16B pad)
#define TILE_BYTES (128 * GROWB)      // 10240 per operand
#define STG_BYTES  (2 * TILE_BYTES)   // 20480 (A then B)
#define GEMM_SMEM  (4 * STG_BYTES)    // 81920 B

__device__ __forceinline__ void g_load_tile(
    uint32_t smb, int stage, int tid,
    const __nv_bfloat16* __restrict__ A, const __nv_bfloat16* __restrict__ W,
    int bm, int k0)
{
    const uint32_t sa = smb + stage * STG_BYTES;
    const uint32_t sb = sa + TILE_BYTES;
    #pragma unroll
    for (int i = 0; i < 2; i++) {
        const int idx = tid + i * 256;
        const int r = idx >> 2, ch = idx & 3;                 // 4 x 16B chunks per 64B row
        cp16(sa + (uint32_t)(r * GROWB + ch * 16), A + (size_t)(bm + r) * 1024 + k0 + ch * 8);
    }
    #pragma unroll
    for (int i = 0; i < 2; i++) {
        const int idx = tid + i * 256;
        const int r = idx >> 2, ch = idx & 3;
        cp16(sb + (uint32_t)(r * GROWB + ch * 16), W + (size_t)r * 1024 + k0 + ch * 8);
    }
}

__global__ void __launch_bounds__(256, 2) gemm_bf16_kernel(
    const __nv_bfloat16* __restrict__ A, const __nv_bfloat16* __restrict__ W,
    const float* __restrict__ bias0, const float* __restrict__ bias1, int bsplit,
    const float* __restrict__ resid, float* __restrict__ C, int ldc)
{
    extern __shared__ char smc[];
    const uint32_t smb = smem_u32(smc);
    const int tid  = threadIdx.x;
    const int warp = tid >> 5, lane = tid & 31;
    const int g = lane >> 2, tl = lane & 3;
    const int lr = lane & 7, lm = lane >> 3;     // ldmatrix row / matrix id
    const int bm = blockIdx.y * GBM;
    const int n0 = blockIdx.x * GBN;
    const int wm = (warp >> 2) << 6;   // 0 or 64
    const int wn = (warp & 3) << 5;    // 0,32,64,96
    const __nv_bfloat16* Wt = W + (size_t)n0 * 1024;
    const float* bias = (n0 < bsplit) ? bias0 + n0 : bias1 + (n0 - bsplit);

    float acc[4][4][4] = {};

    // prologue: stages 0..2
    g_load_tile(smb, 0, tid, A, Wt, bm, 0);
    asm volatile("cp.async.commit_group;" ::: "memory");
    g_load_tile(smb, 1, tid, A, Wt, bm, GBK);
    asm volatile("cp.async.commit_group;" ::: "memory");
    g_load_tile(smb, 2, tid, A, Wt, bm, 2 * GBK);
    asm volatile("cp.async.commit_group;" ::: "memory");

    // precomputed ldmatrix lane offsets
    const uint32_t a_lane_off = (uint32_t)(((lm & 1) * 8 + lr) * GROWB + ((lm >> 1) * 8) * 2);
    const uint32_t b_lane_off = (uint32_t)(((lm >> 1) * 8 + lr) * GROWB + ((lm & 1) * 8) * 2);

    #pragma unroll 1
    for (int t = 0; t < GNT; ++t) {
        asm volatile("cp.async.wait_group 2;" ::: "memory");   // tile t resident
        __syncthreads();                                        // stage (t+3)&3 fully consumed

        const int u = t + 3;
        if (u < GNT) g_load_tile(smb, u & 3, tid, A, Wt, bm, u * GBK);
        asm volatile("cp.async.commit_group;" ::: "memory");

        const uint32_t sA = smb + (t & 3) * STG_BYTES;
        const uint32_t sB = sA + TILE_BYTES;

        #pragma unroll
        for (int kk = 0; kk < GBK; kk += 16) {
            uint32_t a[4][4];
            #pragma unroll
            for (int mi = 0; mi < 4; mi++) {
                const uint32_t addr = sA + (uint32_t)((wm + mi * 16) * GROWB + kk * 2) + a_lane_off;
                ldsm4(a[mi][0], a[mi][1], a[mi][2], a[mi][3], addr);
            }
            #pragma unroll
            for (int nb = 0; nb < 2; nb++) {
                uint32_t b0, b1, b2, b3;
                const uint32_t addr = sB + (uint32_t)((wn + nb * 16) * GROWB + kk * 2) + b_lane_off;
                ldsm4(b0, b1, b2, b3, addr);
                #pragma unroll
                for (int mi = 0; mi < 4; mi++) {
                    mma16(acc[mi][2 * nb],     a[mi], b0, b1);
                    mma16(acc[mi][2 * nb + 1], a[mi], b2, b3);
                }
            }
        }
    }

    // epilogue: bias (+resid), float2 stores
    #pragma unroll
    for (int mi = 0; mi < 4; mi++) {
        const int r0 = bm + wm + mi * 16 + g;
        #pragma unroll
        for (int ni = 0; ni < 4; ni++) {
            const int cl = wn + ni * 8 + 2 * tl;
            const int col = n0 + cl;
            const float bb0 = bias[cl], bb1 = bias[cl + 1];
            float v0 = acc[mi][ni][0] + bb0, v1 = acc[mi][ni][1] + bb1;
            float v2 = acc[mi][ni][2] + bb0, v3 = acc[mi][ni][3] + bb1;
            if (resid) {
                const float2 ra = *(const float2*)(resid + (size_t)r0 * ldc + col);
                const float2 rb = *(const float2*)(resid + (size_t)(r0 + 8) * ldc + col);
                v0 += ra.x; v1 += ra.y; v2 += rb.x; v3 += rb.y;
            }
            *(float2*)(C + (size_t)r0 * ldc + col)       = make_float2(v0, v1);
            *(float2*)(C + (size_t)(r0 + 8) * ldc + col) = make_float2(v2, v3);
        }
    }
}

// ---------------- kernel 3: flash attention (tf32; bf16 output) ----------------
#define AT_STR 68
#define ATTN_SMEM (4 * 64 * AT_STR * 4)   // 69632 B

__global__ void __launch_bounds__(128) attn_kernel(
    const float* __restrict__ qkv, const int* __restrict__ kvlens,
    __nv_bfloat16* __restrict__ attn_out)
{
    extern __shared__ float sma[];
    float (*Qs)[AT_STR] = (float(*)[AT_STR])(sma);
    float (*Ks)[AT_STR] = (float(*)[AT_STR])(sma + 64 * AT_STR);
    float (*Vs)[AT_STR] = (float(*)[AT_STR])(sma + 2 * 64 * AT_STR);
    float (*Ps)[AT_STR] = (float(*)[AT_STR])(sma + 3 * 64 * AT_STR);

    const int qt = blockIdx.x, h = blockIdx.y, b = blockIdx.z;
    const int q0 = qt * 64;
    const int kvlen = kvlens[b];
    const int tid = threadIdx.x, warp = tid >> 5, lane = tid & 31;
    const int g = lane >> 2, t = lane & 3;
    const size_t rowbase = (size_t)b * S_;
    const int hoff = h * DH_;

    #pragma unroll
    for (int i = 0; i < 8; i++) {
        const int idx = tid + i * 128;
        const int r = idx >> 4, c = (idx & 15) << 2;
        const float4 v = *(const float4*)(qkv + (rowbase + q0 + r) * 3072 + hoff + c);
        Qs[r][c + 0] = to_tf32(v.x); Qs[r][c + 1] = to_tf32(v.y);
        Qs[r][c + 2] = to_tf32(v.z); Qs[r][c + 3] = to_tf32(v.w);
    }

    float m_run[2] = { -1e30f, -1e30f };
    float l_run[2] = { 0.f, 0.f };
    float oacc[8][4] = {};

    int kmax = (kvlen - 1) >> 6;
    const int kt_end = (qt < kmax) ? qt : kmax;

    for (int kt = 0; kt <= kt_end; kt++) {
        const int k0 = kt * 64;
        __syncthreads();
        #pragma unroll
        for (int i = 0; i < 8; i++) {
            const int idx = tid + i * 128;
            const int r = idx >> 4, c = (idx & 15) << 2;
            const float4 kv4 = *(const float4*)(qkv + (rowbase + k0 + r) * 3072 + 1024 + hoff + c);
            Ks[r][c + 0] = to_tf32(kv4.x); Ks[r][c + 1] = to_tf32(kv4.y);
            Ks[r][c + 2] = to_tf32(kv4.z); Ks[r][c + 3] = to_tf32(kv4.w);
            const float4 vv4 = *(const float4*)(qkv + (rowbase + k0 + r) * 3072 + 2048 + hoff + c);
            Vs[r][c + 0] = to_tf32(vv4.x); Vs[r][c + 1] = to_tf32(vv4.y);
            Vs[r][c + 2] = to_tf32(vv4.z); Vs[r][c + 3] = to_tf32(vv4.w);
        }
        __syncthreads();

        float s[8][4] = {};
        const int qr = warp * 16 + g;
        #pragma unroll
        for (int kk = 0; kk < 8; kk++) {
            float a[4];
            a[0] = Qs[qr    ][kk * 8 + t];
            a[1] = Qs[qr + 8][kk * 8 + t];
            a[2] = Qs[qr    ][kk * 8 + t + 4];
            a[3] = Qs[qr + 8][kk * 8 + t + 4];
            #pragma unroll
            for (int ni = 0; ni < 8; ni++) {
                float bf[2];
                bf[0] = Ks[ni * 8 + g][kk * 8 + t];
                bf[1] = Ks[ni * 8 + g][kk * 8 + t + 4];
                mma8(s[ni], a, bf);
            }
        }

        const int qrow0 = q0 + qr, qrow1 = qrow0 + 8;
        #pragma unroll
        for (int ni = 0; ni < 8; ni++) {
            const int c0 = k0 + ni * 8 + 2 * t, c1 = c0 + 1;
            s[ni][0] = (c0 <= qrow0 && c0 < kvlen) ? s[ni][0] * 0.125f : -1e30f;
            s[ni][1] = (c1 <= qrow0 && c1 < kvlen) ? s[ni][1] * 0.125f : -1e30f;
            s[ni][2] = (c0 <= qrow1 && c0 < kvlen) ? s[ni][2] * 0.125f : -1e30f;
            s[ni][3] = (c1 <= qrow1 && c1 < kvlen) ? s[ni][3] * 0.125f : -1e30f;
        }

        float mx0 = -1e30f, mx1 = -1e30f;
        #pragma unroll
        for (int ni = 0; ni < 8; ni++) {
            mx0 = fmaxf(mx0, fmaxf(s[ni][0], s[ni][1]));
            mx1 = fmaxf(mx1, fmaxf(s[ni][2], s[ni][3]));
        }
        mx0 = fmaxf(mx0, __shfl_xor_sync(0xffffffffu, mx0, 1));
        mx0 = fmaxf(mx0, __shfl_xor_sync(0xffffffffu, mx0, 2));
        mx1 = fmaxf(mx1, __shfl_xor_sync(0xffffffffu, mx1, 1));
        mx1 = fmaxf(mx1, __shfl_xor_sync(0xffffffffu, mx1, 2));

        const float mn0 = fmaxf(m_run[0], mx0), mn1 = fmaxf(m_run[1], mx1);
        const float al0 = __expf(m_run[0] - mn0), al1 = __expf(m_run[1] - mn1);

        float rs0 = 0.f, rs1 = 0.f;
        #pragma unroll
        for (int ni = 0; ni < 8; ni++) {
            s[ni][0] = __expf(s[ni][0] - mn0); s[ni][1] = __expf(s[ni][1] - mn0);
            s[ni][2] = __expf(s[ni][2] - mn1); s[ni][3] = __expf(s[ni][3] - mn1);
            rs0 += s[ni][0] + s[ni][1];
            rs1 += s[ni][2] + s[ni][3];
        }
        rs0 += __shfl_xor_sync(0xffffffffu, rs0, 1);
        rs0 += __shfl_xor_sync(0xffffffffu, rs0, 2);
        rs1 += __shfl_xor_sync(0xffffffffu, rs1, 1);
        rs1 += __shfl_xor_sync(0xffffffffu, rs1, 2);

        l_run[0] = l_run[0] * al0 + rs0;
        l_run[1] = l_run[1] * al1 + rs1;
        m_run[0] = mn0; m_run[1] = mn1;

        #pragma unroll
        for (int ni = 0; ni < 8; ni++) {
            oacc[ni][0] *= al0; oacc[ni][1] *= al0;
            oacc[ni][2] *= al1; oacc[ni][3] *= al1;
        }

        #pragma unroll
        for (int ni = 0; ni < 8; ni++) {
            Ps[qr    ][ni * 8 + 2 * t]     = to_tf32(s[ni][0]);
            Ps[qr    ][ni * 8 + 2 * t + 1] = to_tf32(s[ni][1]);
            Ps[qr + 8][ni * 8 + 2 * t]     = to_tf32(s[ni][2]);
            Ps[qr + 8][ni * 8 + 2 * t + 1] = to_tf32(s[ni][3]);
        }
        __syncwarp();

        #pragma unroll
        for (int kk = 0; kk < 8; kk++) {
            float a[4];
            a[0] = Ps[qr    ][kk * 8 + t];
            a[1] = Ps[qr + 8][kk * 8 + t];
            a[2] = Ps[qr    ][kk * 8 + t + 4];
            a[3] = Ps[qr + 8][kk * 8 + t + 4];
            #pragma unroll
            for (int ni = 0; ni < 8; ni++) {
                float bf[2];
                bf[0] = Vs[kk * 8 + t    ][ni * 8 + g];
                bf[1] = Vs[kk * 8 + t + 4][ni * 8 + g];
                mma8(oacc[ni], a, bf);
            }
        }
    }

    const float inv0 = 1.f / l_run[0], inv1 = 1.f / l_run[1];
    const int r0 = q0 + warp * 16 + g;
    #pragma unroll
    for (int ni = 0; ni < 8; ni++) {
        const int col = hoff + ni * 8 + 2 * t;
        const __nv_bfloat162 p0 = __floats2bfloat162_rn(oacc[ni][0] * inv0, oacc[ni][1] * inv0);
        const __nv_bfloat162 p1 = __floats2bfloat162_rn(oacc[ni][2] * inv1, oacc[ni][3] * inv1);
        *(__nv_bfloat162*)(attn_out + (rowbase + r0) * 1024 + col)     = p0;
        *(__nv_bfloat162*)(attn_out + (rowbase + r0 + 8) * 1024 + col) = p1;
    }
}

// ---------------- host ----------------
extern "C" void kernel_launch(void* const* d_in, const int* in_sizes, int n_in,
                              void* d_out, int out_size)
{
    (void)in_sizes; (void)n_in; (void)out_size;
    const float* x    = (const float*)d_in[0];
    const int*   kvl  = (const int*)  d_in[1];
    const float* Wq   = (const float*)d_in[2];
    const float* bq   = (const float*)d_in[3];
    const float* Wkv  = (const float*)d_in[4];
    const float* bkv  = (const float*)d_in[5];
    const float* Wo   = (const float*)d_in[6];
    const float* bo   = (const float*)d_in[7];
    const float* ln_g = (const float*)d_in[8];
    const float* ln_b = (const float*)d_in[9];
    float* out = (float*)d_out;

    __nv_bfloat16 *xnb, *attnb, *wqkvb, *wob;
    float *qkv;
    cudaGetSymbolAddress((void**)&xnb,   g_xnb);
    cudaGetSymbolAddress((void**)&qkv,   g_qkv);
    cudaGetSymbolAddress((void**)&attnb, g_attnb);
    cudaGetSymbolAddress((void**)&wqkvb, g_wqkvb);
    cudaGetSymbolAddress((void**)&wob,   g_wob);

    cudaFuncSetAttribute(attn_kernel, cudaFuncAttributeMaxDynamicSharedMemorySize, ATTN_SMEM);
    cudaFuncSetAttribute(gemm_bf16_kernel, cudaFuncAttributeMaxDynamicSharedMemorySize, GEMM_SMEM);

    // 1) layernorm (bf16 out) + weight pack/round (bf16)
    ln_kernel<<<M_, 256>>>(x, ln_g, ln_b, xnb);
    round_w_kernel<<<4096, 256>>>(Wq, Wkv, Wo, wqkvb, wob);

    // 2) fused Q+KV projection: C[8192, 3072] fp32 (ldc 3072)
    gemm_bf16_kernel<<<dim3(3072 / GBN, M_ / GBM), 256, GEMM_SMEM>>>(
        xnb, wqkvb, bq, bkv, 1024, nullptr, qkv, 3072);

    // 3) flash attention (fp32 in, bf16 out)
    attn_kernel<<<dim3(S_ / 64, H_, B_), 128, ATTN_SMEM>>>(qkv, kvl, attnb);

    // 4) output projection + bias + residual (fp32 out)
    gemm_bf16_kernel<<<dim3(1024 / GBN, M_ / GBM), 256, GEMM_SMEM>>>(
        attnb, wob, bo, bo, 1 << 30, x, out, 1024);
}

// round 11
// speedup vs baseline: 1.0002x; 1.0002x over previous
#include <cuda_runtime.h>
#include <cuda_bf16.h>
#include <cstdint>

#define B_  4
#define S_  2048
#define D_  1024
#define H_  16
#define DH_ 64
#define M_  (B_ * S_)   // 8192

// ---------------- scratch (allocation-free: device globals) ----------------
__device__ __nv_bfloat16 g_xnb  [M_ * D_];      // 16 MB, bf16 LN output
__device__ float         g_qkv  [M_ * 3 * D_];  // 96 MB fp32 (Q|K|V)
__device__ __nv_bfloat16 g_attnb[M_ * D_];      // 16 MB, bf16 attention output
__device__ __nv_bfloat16 g_wqkvb[3 * D_ * D_];  // 6 MB, bf16 [Wq;Wkv] (3072x1024 K-major)
__device__ __nv_bfloat16 g_wob  [D_ * D_];      // 2 MB, bf16 Wo

// ---------------- helpers ----------------
__device__ __forceinline__ float to_tf32(float x) {
    uint32_t u;
    asm("cvt.rna.tf32.f32 %0, %1;" : "=r"(u) : "f"(x));
    return __uint_as_float(u);
}

__device__ __forceinline__ uint32_t smem_u32(const void* p) {
    uint32_t a;
    asm("{ .reg .u64 t; cvta.to.shared.u64 t, %1; cvt.u32.u64 %0, t; }" : "=r"(a) : "l"(p));
    return a;
}

__device__ __forceinline__ void cp16(uint32_t dst, const void* src) {
    asm volatile("cp.async.cg.shared.global [%0], [%1], 16;" :: "r"(dst), "l"(src) : "memory");
}

__device__ __forceinline__ void ldsm4(uint32_t& r0, uint32_t& r1, uint32_t& r2, uint32_t& r3,
                                      uint32_t addr) {
    asm volatile("ldmatrix.sync.aligned.m8n8.x4.shared.b16 {%0,%1,%2,%3}, [%4];"
                 : "=r"(r0), "=r"(r1), "=r"(r2), "=r"(r3) : "r"(addr));
}

// D += A(16x16) * B(16x8), bf16 in / f32 accumulate
__device__ __forceinline__ void mma16(float* d, const uint32_t* a, uint32_t b0, uint32_t b1) {
    asm volatile(
        "mma.sync.aligned.m16n8k16.row.col.f32.bf16.bf16.f32 "
        "{%0,%1,%2,%3}, {%4,%5,%6,%7}, {%8,%9}, {%0,%1,%2,%3};\n"
        : "+f"(d[0]), "+f"(d[1]), "+f"(d[2]), "+f"(d[3])
        : "r"(a[0]), "r"(a[1]), "r"(a[2]), "r"(a[3]), "r"(b0), "r"(b1));
}

// legacy tf32 mma for the attention kernel (unchanged)
__device__ __forceinline__ void mma8(float* d, const float* a, const float* b) {
    asm volatile(
        "mma.sync.aligned.m16n8k8.row.col.f32.tf32.tf32.f32 "
        "{%0,%1,%2,%3}, {%4,%5,%6,%7}, {%8,%9}, {%0,%1,%2,%3};\n"
        : "+f"(d[0]), "+f"(d[1]), "+f"(d[2]), "+f"(d[3])
        : "r"(__float_as_uint(a[0])), "r"(__float_as_uint(a[1])),
          "r"(__float_as_uint(a[2])), "r"(__float_as_uint(a[3])),
          "r"(__float_as_uint(b[0])), "r"(__float_as_uint(b[1])));
}

// ---------------- kernel 1: LayerNorm (writes bf16 xn) ----------------
__global__ void __launch_bounds__(256) ln_kernel(
    const float* __restrict__ x, const float* __restrict__ gw,
    const float* __restrict__ bw, __nv_bfloat16* __restrict__ out)
{
    __shared__ float red0[8], red1[8];
    const int row = blockIdx.x;
    const int tid = threadIdx.x;
    const float4 v = ((const float4*)(x + (size_t)row * D_))[tid];

    float s  = v.x + v.y + v.z + v.w;
    float s2 = v.x*v.x + v.y*v.y + v.z*v.z + v.w*v.w;
    #pragma unroll
    for (int o = 16; o; o >>= 1) {
        s  += __shfl_xor_sync(0xffffffffu, s,  o);
        s2 += __shfl_xor_sync(0xffffffffu, s2, o);
    }
    if ((tid & 31) == 0) { red0[tid >> 5] = s; red1[tid >> 5] = s2; }
    __syncthreads();
    s = 0.f; s2 = 0.f;
    #pragma unroll
    for (int i = 0; i < 8; i++) { s += red0[i]; s2 += red1[i]; }

    const float mu  = s * (1.0f / D_);
    float var = s2 * (1.0f / D_) - mu * mu;
    if (var < 0.f) var = 0.f;
    const float r = rsqrtf(var + 1e-5f);

    const float4 g4 = ((const float4*)gw)[tid];
    const float4 b4 = ((const float4*)bw)[tid];
    const __nv_bfloat162 p0 = __floats2bfloat162_rn((v.x - mu) * r * g4.x + b4.x,
                                                    (v.y - mu) * r * g4.y + b4.y);
    const __nv_bfloat162 p1 = __floats2bfloat162_rn((v.z - mu) * r * g4.z + b4.z,
                                                    (v.w - mu) * r * g4.w + b4.w);
    uint2 pk;
    pk.x = *(const uint32_t*)&p0;
    pk.y = *(const uint32_t*)&p1;
    ((uint2*)(out + (size_t)row * D_))[tid] = pk;
}

// ---------------- kernel 1b: pack + round weights to bf16 ----------------
__global__ void __launch_bounds__(256) round_w_kernel(
    const float* __restrict__ Wq, const float* __restrict__ Wkv,
    const float* __restrict__ Wo, __nv_bfloat16* __restrict__ wqkv,
    __nv_bfloat16* __restrict__ wo)
{
    const int i = blockIdx.x * 256 + threadIdx.x;     // float4 index; grid covers 1M
    const int QKV4 = 3 * 1024 * 1024 / 4;             // 786432
    const int Q4   = 1024 * 1024 / 4;                 // 262144
    float4 v;
    __nv_bfloat16* dst;
    int j;
    if (i < QKV4) {
        v = (i < Q4) ? ((const float4*)Wq)[i] : ((const float4*)Wkv)[i - Q4];
        dst = wqkv; j = i;
    } else {
        j = i - QKV4;
        v = ((const float4*)Wo)[j];
        dst = wo;
    }
    const __nv_bfloat162 p0 = __floats2bfloat162_rn(v.x, v.y);
    const __nv_bfloat162 p1 = __floats2bfloat162_rn(v.z, v.w);
    uint2 pk;
    pk.x = *(const uint32_t*)&p0;
    pk.y = *(const uint32_t*)&p1;
    ((uint2*)dst)[j] = pk;
}

// ---------------- kernel 2/4: bf16 mma.m16n8k16 + ldmatrix GEMM ----------------
// C[m,n] = sum_k A[m,k]*W[n,k] + bias[n] (+resid[m,n]);  K = 1024 fixed.
// BM=128, BN=128, BK=32, 4-stage cp.async. 8 warps (2x4), warp tile 64x32.
#define GBM 128
#define GBN 128
#define GBK 32
#define GNT (1024 / GBK)              // 32 k-tiles
#define GROWB 80                      // padded row bytes (32 bf16 = 64B + 16B pad)
#define TILE_BYTES (128 * GROWB)      // 10240 per operand
#define STG_BYTES  (2 * TILE_BYTES)   // 20480 (A then B)
#define GEMM_SMEM  (4 * STG_BYTES)    // 81920 B

__device__ __forceinline__ void g_load_tile(
    uint32_t smb, int stage, int tid,
    const __nv_bfloat16* __restrict__ A, const __nv_bfloat16* __restrict__ W,
    int bm, int k0)
{
    const uint32_t sa = smb + stage * STG_BYTES;
    const uint32_t sb = sa + TILE_BYTES;
    #pragma unroll
    for (int i = 0; i < 2; i++) {
        const int idx = tid + i * 256;
        const int r = idx >> 2, ch = idx & 3;                 // 4 x 16B chunks per 64B row
        cp16(sa + (uint32_t)(r * GROWB + ch * 16), A + (size_t)(bm + r) * 1024 + k0 + ch * 8);
    }
    #pragma unroll
    for (int i = 0; i < 2; i++) {
        const int idx = tid + i * 256;
        const int r = idx >> 2, ch = idx & 3;
        cp16(sb + (uint32_t)(r * GROWB + ch * 16), W + (size_t)r * 1024 + k0 + ch * 8);
    }
}

__global__ void __launch_bounds__(256, 2) gemm_bf16_kernel(
    const __nv_bfloat16* __restrict__ A, const __nv_bfloat16* __restrict__ W,
    const float* __restrict__ bias0, const float* __restrict__ bias1, int bsplit,
    const float* __restrict__ resid, float* __restrict__ C, int ldc)
{
    extern __shared__ char smc[];
    const uint32_t smb = smem_u32(smc);
    const int tid  = threadIdx.x;
    const int warp = tid >> 5, lane = tid & 31;
    const int g = lane >> 2, tl = lane & 3;
    const int lr = lane & 7, lm = lane >> 3;     // ldmatrix row / matrix id
    const int bm = blockIdx.y * GBM;
    const int n0 = blockIdx.x * GBN;
    const int wm = (warp >> 2) << 6;   // 0 or 64
    const int wn = (warp & 3) << 5;    // 0,32,64,96
    const __nv_bfloat16* Wt = W + (size_t)n0 * 1024;
    const float* bias = (n0 < bsplit) ? bias0 + n0 : bias1 + (n0 - bsplit);

    float acc[4][4][4] = {};

    // prologue: stages 0..2
    g_load_tile(smb, 0, tid, A, Wt, bm, 0);
    asm volatile("cp.async.commit_group;" ::: "memory");
    g_load_tile(smb, 1, tid, A, Wt, bm, GBK);
    asm volatile("cp.async.commit_group;" ::: "memory");
    g_load_tile(smb, 2, tid, A, Wt, bm, 2 * GBK);
    asm volatile("cp.async.commit_group;" ::: "memory");

    // precomputed ldmatrix lane offsets
    const uint32_t a_lane_off = (uint32_t)(((lm & 1) * 8 + lr) * GROWB + ((lm >> 1) * 8) * 2);
    const uint32_t b_lane_off = (uint32_t)(((lm >> 1) * 8 + lr) * GROWB + ((lm & 1) * 8) * 2);

    #pragma unroll 1
    for (int t = 0; t < GNT; ++t) {
        asm volatile("cp.async.wait_group 2;" ::: "memory");   // tile t resident
        __syncthreads();                                        // stage (t+3)&3 fully consumed

        const int u = t + 3;
        if (u < GNT) g_load_tile(smb, u & 3, tid, A, Wt, bm, u * GBK);
        asm volatile("cp.async.commit_group;" ::: "memory");

        const uint32_t sA = smb + (t & 3) * STG_BYTES;
        const uint32_t sB = sA + TILE_BYTES;

        #pragma unroll
        for (int kk = 0; kk < GBK; kk += 16) {
            uint32_t a[4][4];
            #pragma unroll
            for (int mi = 0; mi < 4; mi++) {
                const uint32_t addr = sA + (uint32_t)((wm + mi * 16) * GROWB + kk * 2) + a_lane_off;
                ldsm4(a[mi][0], a[mi][1], a[mi][2], a[mi][3], addr);
            }
            #pragma unroll
            for (int nb = 0; nb < 2; nb++) {
                uint32_t b0, b1, b2, b3;
                const uint32_t addr = sB + (uint32_t)((wn + nb * 16) * GROWB + kk * 2) + b_lane_off;
                ldsm4(b0, b1, b2, b3, addr);
                #pragma unroll
                for (int mi = 0; mi < 4; mi++) {
                    mma16(acc[mi][2 * nb],     a[mi], b0, b1);
                    mma16(acc[mi][2 * nb + 1], a[mi], b2, b3);
                }
            }
        }
    }

    // epilogue: bias (+resid), float2 stores
    #pragma unroll
    for (int mi = 0; mi < 4; mi++) {
        const int r0 = bm + wm + mi * 16 + g;
        #pragma unroll
        for (int ni = 0; ni < 4; ni++) {
            const int cl = wn + ni * 8 + 2 * tl;
            const int col = n0 + cl;
            const float bb0 = bias[cl], bb1 = bias[cl + 1];
            float v0 = acc[mi][ni][0] + bb0, v1 = acc[mi][ni][1] + bb1;
            float v2 = acc[mi][ni][2] + bb0, v3 = acc[mi][ni][3] + bb1;
            if (resid) {
                const float2 ra = *(const float2*)(resid + (size_t)r0 * ldc + col);
                const float2 rb = *(const float2*)(resid + (size_t)(r0 + 8) * ldc + col);
                v0 += ra.x; v1 += ra.y; v2 += rb.x; v3 += rb.y;
            }
            *(float2*)(C + (size_t)r0 * ldc + col)       = make_float2(v0, v1);
            *(float2*)(C + (size_t)(r0 + 8) * ldc + col) = make_float2(v2, v3);
        }
    }
}

// ---------------- kernel 3: flash attention (tf32; bf16 output) ----------------
#define AT_STR 68
#define ATTN_SMEM (4 * 64 * AT_STR * 4)   // 69632 B

__global__ void __launch_bounds__(128) attn_kernel(
    const float* __restrict__ qkv, const int* __restrict__ kvlens,
    __nv_bfloat16* __restrict__ attn_out)
{
    extern __shared__ float sma[];
    float (*Qs)[AT_STR] = (float(*)[AT_STR])(sma);
    float (*Ks)[AT_STR] = (float(*)[AT_STR])(sma + 64 * AT_STR);
    float (*Vs)[AT_STR] = (float(*)[AT_STR])(sma + 2 * 64 * AT_STR);
    float (*Ps)[AT_STR] = (float(*)[AT_STR])(sma + 3 * 64 * AT_STR);

    const int qt = blockIdx.x, h = blockIdx.y, b = blockIdx.z;
    const int q0 = qt * 64;
    const int kvlen = kvlens[b];
    const int tid = threadIdx.x, warp = tid >> 5, lane = tid & 31;
    const int g = lane >> 2, t = lane & 3;
    const size_t rowbase = (size_t)b * S_;
    const int hoff = h * DH_;

    #pragma unroll
    for (int i = 0; i < 8; i++) {
        const int idx = tid + i * 128;
        const int r = idx >> 4, c = (idx & 15) << 2;
        const float4 v = *(const float4*)(qkv + (rowbase + q0 + r) * 3072 + hoff + c);
        Qs[r][c + 0] = to_tf32(v.x); Qs[r][c + 1] = to_tf32(v.y);
        Qs[r][c + 2] = to_tf32(v.z); Qs[r][c + 3] = to_tf32(v.w);
    }

    float m_run[2] = { -1e30f, -1e30f };
    float l_run[2] = { 0.f, 0.f };
    float oacc[8][4] = {};

    int kmax = (kvlen - 1) >> 6;
    const int kt_end = (qt < kmax) ? qt : kmax;

    for (int kt = 0; kt <= kt_end; kt++) {
        const int k0 = kt * 64;
        __syncthreads();
        #pragma unroll
        for (int i = 0; i < 8; i++) {
            const int idx = tid + i * 128;
            const int r = idx >> 4, c = (idx & 15) << 2;
            const float4 kv4 = *(const float4*)(qkv + (rowbase + k0 + r) * 3072 + 1024 + hoff + c);
            Ks[r][c + 0] = to_tf32(kv4.x); Ks[r][c + 1] = to_tf32(kv4.y);
            Ks[r][c + 2] = to_tf32(kv4.z); Ks[r][c + 3] = to_tf32(kv4.w);
            const float4 vv4 = *(const float4*)(qkv + (rowbase + k0 + r) * 3072 + 2048 + hoff + c);
            Vs[r][c + 0] = to_tf32(vv4.x); Vs[r][c + 1] = to_tf32(vv4.y);
            Vs[r][c + 2] = to_tf32(vv4.z); Vs[r][c + 3] = to_tf32(vv4.w);
        }
        __syncthreads();

        float s[8][4] = {};
        const int qr = warp * 16 + g;
        #pragma unroll
        for (int kk = 0; kk < 8; kk++) {
            float a[4];
            a[0] = Qs[qr    ][kk * 8 + t];
            a[1] = Qs[qr + 8][kk * 8 + t];
            a[2] = Qs[qr    ][kk * 8 + t + 4];
            a[3] = Qs[qr + 8][kk * 8 + t + 4];
            #pragma unroll
            for (int ni = 0; ni < 8; ni++) {
                float bf[2];
                bf[0] = Ks[ni * 8 + g][kk * 8 + t];
                bf[1] = Ks[ni * 8 + g][kk * 8 + t + 4];
                mma8(s[ni], a, bf);
            }
        }

        const int qrow0 = q0 + qr, qrow1 = qrow0 + 8;
        #pragma unroll
        for (int ni = 0; ni < 8; ni++) {
            const int c0 = k0 + ni * 8 + 2 * t, c1 = c0 + 1;
            s[ni][0] = (c0 <= qrow0 && c0 < kvlen) ? s[ni][0] * 0.125f : -1e30f;
            s[ni][1] = (c1 <= qrow0 && c1 < kvlen) ? s[ni][1] * 0.125f : -1e30f;
            s[ni][2] = (c0 <= qrow1 && c0 < kvlen) ? s[ni][2] * 0.125f : -1e30f;
            s[ni][3] = (c1 <= qrow1 && c1 < kvlen) ? s[ni][3] * 0.125f : -1e30f;
        }

        float mx0 = -1e30f, mx1 = -1e30f;
        #pragma unroll
        for (int ni = 0; ni < 8; ni++) {
            mx0 = fmaxf(mx0, fmaxf(s[ni][0], s[ni][1]));
            mx1 = fmaxf(mx1, fmaxf(s[ni][2], s[ni][3]));
        }
        mx0 = fmaxf(mx0, __shfl_xor_sync(0xffffffffu, mx0, 1));
        mx0 = fmaxf(mx0, __shfl_xor_sync(0xffffffffu, mx0, 2));
        mx1 = fmaxf(mx1, __shfl_xor_sync(0xffffffffu, mx1, 1));
        mx1 = fmaxf(mx1, __shfl_xor_sync(0xffffffffu, mx1, 2));

        const float mn0 = fmaxf(m_run[0], mx0), mn1 = fmaxf(m_run[1], mx1);
        const float al0 = __expf(m_run[0] - mn0), al1 = __expf(m_run[1] - mn1);

        float rs0 = 0.f, rs1 = 0.f;
        #pragma unroll
        for (int ni = 0; ni < 8; ni++) {
            s[ni][0] = __expf(s[ni][0] - mn0); s[ni][1] = __expf(s[ni][1] - mn0);
            s[ni][2] = __expf(s[ni][2] - mn1); s[ni][3] = __expf(s[ni][3] - mn1);
            rs0 += s[ni][0] + s[ni][1];
            rs1 += s[ni][2] + s[ni][3];
        }
        rs0 += __shfl_xor_sync(0xffffffffu, rs0, 1);
        rs0 += __shfl_xor_sync(0xffffffffu, rs0, 2);
        rs1 += __shfl_xor_sync(0xffffffffu, rs1, 1);
        rs1 += __shfl_xor_sync(0xffffffffu, rs1, 2);

        l_run[0] = l_run[0] * al0 + rs0;
        l_run[1] = l_run[1] * al1 + rs1;
        m_run[0] = mn0; m_run[1] = mn1;

        #pragma unroll
        for (int ni = 0; ni < 8; ni++) {
            oacc[ni][0] *= al0; oacc[ni][1] *= al0;
            oacc[ni][2] *= al1; oacc[ni][3] *= al1;
        }

        #pragma unroll
        for (int ni = 0; ni < 8; ni++) {
            Ps[qr    ][ni * 8 + 2 * t]     = to_tf32(s[ni][0]);
            Ps[qr    ][ni * 8 + 2 * t + 1] = to_tf32(s[ni][1]);
            Ps[qr + 8][ni * 8 + 2 * t]     = to_tf32(s[ni][2]);
            Ps[qr + 8][ni * 8 + 2 * t + 1] = to_tf32(s[ni][3]);
        }
        __syncwarp();

        #pragma unroll
        for (int kk = 0; kk < 8; kk++) {
            float a[4];
            a[0] = Ps[qr    ][kk * 8 + t];
            a[1] = Ps[qr + 8][kk * 8 + t];
            a[2] = Ps[qr    ][kk * 8 + t + 4];
            a[3] = Ps[qr + 8][kk * 8 + t + 4];
            #pragma unroll
            for (int ni = 0; ni < 8; ni++) {
                float bf[2];
                bf[0] = Vs[kk * 8 + t    ][ni * 8 + g];
                bf[1] = Vs[kk * 8 + t + 4][ni * 8 + g];
                mma8(oacc[ni], a, bf);
            }
        }
    }

    const float inv0 = 1.f / l_run[0], inv1 = 1.f / l_run[1];
    const int r0 = q0 + warp * 16 + g;
    #pragma unroll
    for (int ni = 0; ni < 8; ni++) {
        const int col = hoff + ni * 8 + 2 * t;
        const __nv_bfloat162 p0 = __floats2bfloat162_rn(oacc[ni][0] * inv0, oacc[ni][1] * inv0);
        const __nv_bfloat162 p1 = __floats2bfloat162_rn(oacc[ni][2] * inv1, oacc[ni][3] * inv1);
        *(__nv_bfloat162*)(attn_out + (rowbase + r0) * 1024 + col)     = p0;
        *(__nv_bfloat162*)(attn_out + (rowbase + r0 + 8) * 1024 + col) = p1;
    }
}

// ---------------- host ----------------
extern "C" void kernel_launch(void* const* d_in, const int* in_sizes, int n_in,
                              void* d_out, int out_size)
{
    (void)in_sizes; (void)n_in; (void)out_size;
    const float* x    = (const float*)d_in[0];
    const int*   kvl  = (const int*)  d_in[1];
    const float* Wq   = (const float*)d_in[2];
    const float* bq   = (const float*)d_in[3];
    const float* Wkv  = (const float*)d_in[4];
    const float* bkv  = (const float*)d_in[5];
    const float* Wo   = (const float*)d_in[6];
    const float* bo   = (const float*)d_in[7];
    const float* ln_g = (const float*)d_in[8];
    const float* ln_b = (const float*)d_in[9];
    float* out = (float*)d_out;

    __nv_bfloat16 *xnb, *attnb, *wqkvb, *wob;
    float *qkv;
    cudaGetSymbolAddress((void**)&xnb,   g_xnb);
    cudaGetSymbolAddress((void**)&qkv,   g_qkv);
    cudaGetSymbolAddress((void**)&attnb, g_attnb);
    cudaGetSymbolAddress((void**)&wqkvb, g_wqkvb);
    cudaGetSymbolAddress((void**)&wob,   g_wob);

    cudaFuncSetAttribute(attn_kernel, cudaFuncAttributeMaxDynamicSharedMemorySize, ATTN_SMEM);
    cudaFuncSetAttribute(gemm_bf16_kernel, cudaFuncAttributeMaxDynamicSharedMemorySize, GEMM_SMEM);

    // 1) layernorm (bf16 out) + weight pack/round (bf16)
    ln_kernel<<<M_, 256>>>(x, ln_g, ln_b, xnb);
    round_w_kernel<<<4096, 256>>>(Wq, Wkv, Wo, wqkvb, wob);

    // 2) fused Q+KV projection: C[8192, 3072] fp32 (ldc 3072)
    gemm_bf16_kernel<<<dim3(3072 / GBN, M_ / GBM), 256, GEMM_SMEM>>>(
        xnb, wqkvb, bq, bkv, 1024, nullptr, qkv, 3072);

    // 3) flash attention (fp32 in, bf16 out)
    attn_kernel<<<dim3(S_ / 64, H_, B_), 128, ATTN_SMEM>>>(qkv, kvl, attnb);

    // 4) output projection + bias + residual (fp32 out)
    gemm_bf16_kernel<<<dim3(1024 / GBN, M_ / GBM), 256, GEMM_SMEM>>>(
        attnb, wob, bo, bo, 1 << 30, x, out, 1024);
}

// round 12
// speedup vs baseline: 1.0006x; 1.0003x over previous
#include <cuda_runtime.h>
#include <cuda_bf16.h>
#include <cstdint>

#define B_  4
#define S_  2048
#define D_  1024
#define H_  16
#define DH_ 64
#define M_  (B_ * S_)   // 8192

// ---------------- scratch (allocation-free: device globals) ----------------
__device__ __nv_bfloat16 g_xnb  [M_ * D_];      // 16 MB, bf16 LN output
__device__ float         g_qkv  [M_ * 3 * D_];  // 96 MB fp32 (Q|K|V)
__device__ __nv_bfloat16 g_attnb[M_ * D_];      // 16 MB, bf16 attention output
__device__ __nv_bfloat16 g_wqkvb[3 * D_ * D_];  // 6 MB, bf16 [Wq;Wkv] (3072x1024 K-major)
__device__ __nv_bfloat16 g_wob  [D_ * D_];      // 2 MB, bf16 Wo

// ---------------- helpers ----------------
__device__ __forceinline__ float to_tf32(float x) {
    uint32_t u;
    asm("cvt.rna.tf32.f32 %0, %1;" : "=r"(u) : "f"(x));
    return __uint_as_float(u);
}

__device__ __forceinline__ uint32_t smem_u32(const void* p) {
    uint32_t a;
    asm("{ .reg .u64 t; cvta.to.shared.u64 t, %1; cvt.u32.u64 %0, t; }" : "=r"(a) : "l"(p));
    return a;
}

__device__ __forceinline__ void cp16(uint32_t dst, const void* src) {
    asm volatile("cp.async.cg.shared.global [%0], [%1], 16;" :: "r"(dst), "l"(src) : "memory");
}

__device__ __forceinline__ void ldsm4(uint32_t& r0, uint32_t& r1, uint32_t& r2, uint32_t& r3,
                                      uint32_t addr) {
    asm volatile("ldmatrix.sync.aligned.m8n8.x4.shared.b16 {%0,%1,%2,%3}, [%4];"
                 : "=r"(r0), "=r"(r1), "=r"(r2), "=r"(r3) : "r"(addr));
}

// D += A(16x16) * B(16x8), bf16 in / f32 accumulate
__device__ __forceinline__ void mma16(float* d, const uint32_t* a, uint32_t b0, uint32_t b1) {
    asm volatile(
        "mma.sync.aligned.m16n8k16.row.col.f32.bf16.bf16.f32 "
        "{%0,%1,%2,%3}, {%4,%5,%6,%7}, {%8,%9}, {%0,%1,%2,%3};\n"
        : "+f"(d[0]), "+f"(d[1]), "+f"(d[2]), "+f"(d[3])
        : "r"(a[0]), "r"(a[1]), "r"(a[2]), "r"(a[3]), "r"(b0), "r"(b1));
}

// legacy tf32 mma for the attention kernel (unchanged)
__device__ __forceinline__ void mma8(float* d, const float* a, const float* b) {
    asm volatile(
        "mma.sync.aligned.m16n8k8.row.col.f32.tf32.tf32.f32 "
        "{%0,%1,%2,%3}, {%4,%5,%6,%7}, {%8,%9}, {%0,%1,%2,%3};\n"
        : "+f"(d[0]), "+f"(d[1]), "+f"(d[2]), "+f"(d[3])
        : "r"(__float_as_uint(a[0])), "r"(__float_as_uint(a[1])),
          "r"(__float_as_uint(a[2])), "r"(__float_as_uint(a[3])),
          "r"(__float_as_uint(b[0])), "r"(__float_as_uint(b[1])));
}

// ---------------- kernel 1: LayerNorm (writes bf16 xn) ----------------
__global__ void __launch_bounds__(256) ln_kernel(
    const float* __restrict__ x, const float* __restrict__ gw,
    const float* __restrict__ bw, __nv_bfloat16* __restrict__ out)
{
    __shared__ float red0[8], red1[8];
    const int row = blockIdx.x;
    const int tid = threadIdx.x;
    const float4 v = ((const float4*)(x + (size_t)row * D_))[tid];

    float s  = v.x + v.y + v.z + v.w;
    float s2 = v.x*v.x + v.y*v.y + v.z*v.z + v.w*v.w;
    #pragma unroll
    for (int o = 16; o; o >>= 1) {
        s  += __shfl_xor_sync(0xffffffffu, s,  o);
        s2 += __shfl_xor_sync(0xffffffffu, s2, o);
    }
    if ((tid & 31) == 0) { red0[tid >> 5] = s; red1[tid >> 5] = s2; }
    __syncthreads();
    s = 0.f; s2 = 0.f;
    #pragma unroll
    for (int i = 0; i < 8; i++) { s += red0[i]; s2 += red1[i]; }

    const float mu  = s * (1.0f / D_);
    float var = s2 * (1.0f / D_) - mu * mu;
    if (var < 0.f) var = 0.f;
    const float r = rsqrtf(var + 1e-5f);

    const float4 g4 = ((const float4*)gw)[tid];
    const float4 b4 = ((const float4*)bw)[tid];
    const __nv_bfloat162 p0 = __floats2bfloat162_rn((v.x - mu) * r * g4.x + b4.x,
                                                    (v.y - mu) * r * g4.y + b4.y);
    const __nv_bfloat162 p1 = __floats2bfloat162_rn((v.z - mu) * r * g4.z + b4.z,
                                                    (v.w - mu) * r * g4.w + b4.w);
    uint2 pk;
    pk.x = *(const uint32_t*)&p0;
    pk.y = *(const uint32_t*)&p1;
    ((uint2*)(out + (size_t)row * D_))[tid] = pk;
}

// ---------------- kernel 1b: pack + round weights to bf16 ----------------
__global__ void __launch_bounds__(256) round_w_kernel(
    const float* __restrict__ Wq, const float* __restrict__ Wkv,
    const float* __restrict__ Wo, __nv_bfloat16* __restrict__ wqkv,
    __nv_bfloat16* __restrict__ wo)
{
    const int i = blockIdx.x * 256 + threadIdx.x;     // float4 index; grid covers 1M
    const int QKV4 = 3 * 1024 * 1024 / 4;             // 786432
    const int Q4   = 1024 * 1024 / 4;                 // 262144
    float4 v;
    __nv_bfloat16* dst;
    int j;
    if (i < QKV4) {
        v = (i < Q4) ? ((const float4*)Wq)[i] : ((const float4*)Wkv)[i - Q4];
        dst = wqkv; j = i;
    } else {
        j = i - QKV4;
        v = ((const float4*)Wo)[j];
        dst = wo;
    }
    const __nv_bfloat162 p0 = __floats2bfloat162_rn(v.x, v.y);
    const __nv_bfloat162 p1 = __floats2bfloat162_rn(v.z, v.w);
    uint2 pk;
    pk.x = *(const uint32_t*)&p0;
    pk.y = *(const uint32_t*)&p1;
    ((uint2*)dst)[j] = pk;
}

// ---------------- kernel 2/4: bf16 mma.m16n8k16 + ldmatrix GEMM ----------------
// C[m,n] = sum_k A[m,k]*W[n,k] + bias[n] (+resid[m,n]);  K = 1024 fixed.
// BM=128, BN=128, BK=32, 4-stage cp.async. 8 warps (2x4), warp tile 64x32.
#define GBM 128
#define GBN 128
#define GBK 32
#define GNT (1024 / GBK)              // 32 k-tiles
#define GROWB 80                      // padded row bytes (32 bf16 = 64B + 16B pad)
#define TILE_BYTES (128 * GROWB)      // 10240 per operand
#define STG_BYTES  (2 * TILE_BYTES)   // 20480 (A then B)
#define GEMM_SMEM  (4 * STG_BYTES)    // 81920 B

__device__ __forceinline__ void g_load_tile(
    uint32_t smb, int stage, int tid,
    const __nv_bfloat16* __restrict__ A, const __nv_bfloat16* __restrict__ W,
    int bm, int k0)
{
    const uint32_t sa = smb + stage * STG_BYTES;
    const uint32_t sb = sa + TILE_BYTES;
    #pragma unroll
    for (int i = 0; i < 2; i++) {
        const int idx = tid + i * 256;
        const int r = idx >> 2, ch = idx & 3;                 // 4 x 16B chunks per 64B row
        cp16(sa + (uint32_t)(r * GROWB + ch * 16), A + (size_t)(bm + r) * 1024 + k0 + ch * 8);
    }
    #pragma unroll
    for (int i = 0; i < 2; i++) {
        const int idx = tid + i * 256;
        const int r = idx >> 2, ch = idx & 3;
        cp16(sb + (uint32_t)(r * GROWB + ch * 16), W + (size_t)r * 1024 + k0 + ch * 8);
    }
}

__global__ void __launch_bounds__(256, 2) gemm_bf16_kernel(
    const __nv_bfloat16* __restrict__ A, const __nv_bfloat16* __restrict__ W,
    const float* __restrict__ bias0, const float* __restrict__ bias1, int bsplit,
    const float* __restrict__ resid, float* __restrict__ C, int ldc)
{
    extern __shared__ char smc[];
    const uint32_t smb = smem_u32(smc);
    const int tid  = threadIdx.x;
    const int warp = tid >> 5, lane = tid & 31;
    const int g = lane >> 2, tl = lane & 3;
    const int lr = lane & 7, lm = lane >> 3;     // ldmatrix row / matrix id
    const int bm = blockIdx.y * GBM;
    const int n0 = blockIdx.x * GBN;
    const int wm = (warp >> 2) << 6;   // 0 or 64
    const int wn = (warp & 3) << 5;    // 0,32,64,96
    const __nv_bfloat16* Wt = W + (size_t)n0 * 1024;
    const float* bias = (n0 < bsplit) ? bias0 + n0 : bias1 + (n0 - bsplit);

    float acc[4][4][4] = {};

    // prologue: stages 0..2
    g_load_tile(smb, 0, tid, A, Wt, bm, 0);
    asm volatile("cp.async.commit_group;" ::: "memory");
    g_load_tile(smb, 1, tid, A, Wt, bm, GBK);
    asm volatile("cp.async.commit_group;" ::: "memory");
    g_load_tile(smb, 2, tid, A, Wt, bm, 2 * GBK);
    asm volatile("cp.async.commit_group;" ::: "memory");

    // precomputed ldmatrix lane offsets
    const uint32_t a_lane_off = (uint32_t)(((lm & 1) * 8 + lr) * GROWB + ((lm >> 1) * 8) * 2);
    const uint32_t b_lane_off = (uint32_t)(((lm >> 1) * 8 + lr) * GROWB + ((lm & 1) * 8) * 2);

    #pragma unroll 1
    for (int t = 0; t < GNT; ++t) {
        asm volatile("cp.async.wait_group 2;" ::: "memory");   // tile t resident
        __syncthreads();                                        // stage (t+3)&3 fully consumed

        const int u = t + 3;
        if (u < GNT) g_load_tile(smb, u & 3, tid, A, Wt, bm, u * GBK);
        asm volatile("cp.async.commit_group;" ::: "memory");

        const uint32_t sA = smb + (t & 3) * STG_BYTES;
        const uint32_t sB = sA + TILE_BYTES;

        #pragma unroll
        for (int kk = 0; kk < GBK; kk += 16) {
            uint32_t a[4][4];
            #pragma unroll
            for (int mi = 0; mi < 4; mi++) {
                const uint32_t addr = sA + (uint32_t)((wm + mi * 16) * GROWB + kk * 2) + a_lane_off;
                ldsm4(a[mi][0], a[mi][1], a[mi][2], a[mi][3], addr);
            }
            #pragma unroll
            for (int nb = 0; nb < 2; nb++) {
                uint32_t b0, b1, b2, b3;
                const uint32_t addr = sB + (uint32_t)((wn + nb * 16) * GROWB + kk * 2) + b_lane_off;
                ldsm4(b0, b1, b2, b3, addr);
                #pragma unroll
                for (int mi = 0; mi < 4; mi++) {
                    mma16(acc[mi][2 * nb],     a[mi], b0, b1);
                    mma16(acc[mi][2 * nb + 1], a[mi], b2, b3);
                }
            }
        }
    }

    // epilogue: bias (+resid), float2 stores
    #pragma unroll
    for (int mi = 0; mi < 4; mi++) {
        const int r0 = bm + wm + mi * 16 + g;
        #pragma unroll
        for (int ni = 0; ni < 4; ni++) {
            const int cl = wn + ni * 8 + 2 * tl;
            const int col = n0 + cl;
            const float bb0 = bias[cl], bb1 = bias[cl + 1];
            float v0 = acc[mi][ni][0] + bb0, v1 = acc[mi][ni][1] + bb1;
            float v2 = acc[mi][ni][2] + bb0, v3 = acc[mi][ni][3] + bb1;
            if (resid) {
                const float2 ra = *(const float2*)(resid + (size_t)r0 * ldc + col);
                const float2 rb = *(const float2*)(resid + (size_t)(r0 + 8) * ldc + col);
                v0 += ra.x; v1 += ra.y; v2 += rb.x; v3 += rb.y;
            }
            *(float2*)(C + (size_t)r0 * ldc + col)       = make_float2(v0, v1);
            *(float2*)(C + (size_t)(r0 + 8) * ldc + col) = make_float2(v2, v3);
        }
    }
}

// ---------------- kernel 3: flash attention (tf32; bf16 output) ----------------
#define AT_STR 68
#define ATTN_SMEM (4 * 64 * AT_STR * 4)   // 69632 B

__global__ void __launch_bounds__(128) attn_kernel(
    const float* __restrict__ qkv, const int* __restrict__ kvlens,
    __nv_bfloat16* __restrict__ attn_out)
{
    extern __shared__ float sma[];
    float (*Qs)[AT_STR] = (float(*)[AT_STR])(sma);
    float (*Ks)[AT_STR] = (float(*)[AT_STR])(sma + 64 * AT_STR);
    float (*Vs)[AT_STR] = (float(*)[AT_STR])(sma + 2 * 64 * AT_STR);
    float (*Ps)[AT_STR] = (float(*)[AT_STR])(sma + 3 * 64 * AT_STR);

    const int qt = blockIdx.x, h = blockIdx.y, b = blockIdx.z;
    const int q0 = qt * 64;
    const int kvlen = kvlens[b];
    const int tid = threadIdx.x, warp = tid >> 5, lane = tid & 31;
    const int g = lane >> 2, t = lane & 3;
    const size_t rowbase = (size_t)b * S_;
    const int hoff = h * DH_;

    #pragma unroll
    for (int i = 0; i < 8; i++) {
        const int idx = tid + i * 128;
        const int r = idx >> 4, c = (idx & 15) << 2;
        const float4 v = *(const float4*)(qkv + (rowbase + q0 + r) * 3072 + hoff + c);
        Qs[r][c + 0] = to_tf32(v.x); Qs[r][c + 1] = to_tf32(v.y);
        Qs[r][c + 2] = to_tf32(v.z); Qs[r][c + 3] = to_tf32(v.w);
    }

    float m_run[2] = { -1e30f, -1e30f };
    float l_run[2] = { 0.f, 0.f };
    float oacc[8][4] = {};

    int kmax = (kvlen - 1) >> 6;
    const int kt_end = (qt < kmax) ? qt : kmax;

    for (int kt = 0; kt <= kt_end; kt++) {
        const int k0 = kt * 64;
        __syncthreads();
        #pragma unroll
        for (int i = 0; i < 8; i++) {
            const int idx = tid + i * 128;
            const int r = idx >> 4, c = (idx & 15) << 2;
            const float4 kv4 = *(const float4*)(qkv + (rowbase + k0 + r) * 3072 + 1024 + hoff + c);
            Ks[r][c + 0] = to_tf32(kv4.x); Ks[r][c + 1] = to_tf32(kv4.y);
            Ks[r][c + 2] = to_tf32(kv4.z); Ks[r][c + 3] = to_tf32(kv4.w);
            const float4 vv4 = *(const float4*)(qkv + (rowbase + k0 + r) * 3072 + 2048 + hoff + c);
            Vs[r][c + 0] = to_tf32(vv4.x); Vs[r][c + 1] = to_tf32(vv4.y);
            Vs[r][c + 2] = to_tf32(vv4.z); Vs[r][c + 3] = to_tf32(vv4.w);
        }
        __syncthreads();

        float s[8][4] = {};
        const int qr = warp * 16 + g;
        #pragma unroll
        for (int kk = 0; kk < 8; kk++) {
            float a[4];
            a[0] = Qs[qr    ][kk * 8 + t];
            a[1] = Qs[qr + 8][kk * 8 + t];
            a[2] = Qs[qr    ][kk * 8 + t + 4];
            a[3] = Qs[qr + 8][kk * 8 + t + 4];
            #pragma unroll
            for (int ni = 0; ni < 8; ni++) {
                float bf[2];
                bf[0] = Ks[ni * 8 + g][kk * 8 + t];
                bf[1] = Ks[ni * 8 + g][kk * 8 + t + 4];
                mma8(s[ni], a, bf);
            }
        }

        const int qrow0 = q0 + qr, qrow1 = qrow0 + 8;
        #pragma unroll
        for (int ni = 0; ni < 8; ni++) {
            const int c0 = k0 + ni * 8 + 2 * t, c1 = c0 + 1;
            s[ni][0] = (c0 <= qrow0 && c0 < kvlen) ? s[ni][0] * 0.125f : -1e30f;
            s[ni][1] = (c1 <= qrow0 && c1 < kvlen) ? s[ni][1] * 0.125f : -1e30f;
            s[ni][2] = (c0 <= qrow1 && c0 < kvlen) ? s[ni][2] * 0.125f : -1e30f;
            s[ni][3] = (c1 <= qrow1 && c1 < kvlen) ? s[ni][3] * 0.125f : -1e30f;
        }

        float mx0 = -1e30f, mx1 = -1e30f;
        #pragma unroll
        for (int ni = 0; ni < 8; ni++) {
            mx0 = fmaxf(mx0, fmaxf(s[ni][0], s[ni][1]));
            mx1 = fmaxf(mx1, fmaxf(s[ni][2], s[ni][3]));
        }
        mx0 = fmaxf(mx0, __shfl_xor_sync(0xffffffffu, mx0, 1));
        mx0 = fmaxf(mx0, __shfl_xor_sync(0xffffffffu, mx0, 2));
        mx1 = fmaxf(mx1, __shfl_xor_sync(0xffffffffu, mx1, 1));
        mx1 = fmaxf(mx1, __shfl_xor_sync(0xffffffffu, mx1, 2));

        const float mn0 = fmaxf(m_run[0], mx0), mn1 = fmaxf(m_run[1], mx1);
        const float al0 = __expf(m_run[0] - mn0), al1 = __expf(m_run[1] - mn1);

        float rs0 = 0.f, rs1 = 0.f;
        #pragma unroll
        for (int ni = 0; ni < 8; ni++) {
            s[ni][0] = __expf(s[ni][0] - mn0); s[ni][1] = __expf(s[ni][1] - mn0);
            s[ni][2] = __expf(s[ni][2] - mn1); s[ni][3] = __expf(s[ni][3] - mn1);
            rs0 += s[ni][0] + s[ni][1];
            rs1 += s[ni][2] + s[ni][3];
        }
        rs0 += __shfl_xor_sync(0xffffffffu, rs0, 1);
        rs0 += __shfl_xor_sync(0xffffffffu, rs0, 2);
        rs1 += __shfl_xor_sync(0xffffffffu, rs1, 1);
        rs1 += __shfl_xor_sync(0xffffffffu, rs1, 2);

        l_run[0] = l_run[0] * al0 + rs0;
        l_run[1] = l_run[1] * al1 + rs1;
        m_run[0] = mn0; m_run[1] = mn1;

        #pragma unroll
        for (int ni = 0; ni < 8; ni++) {
            oacc[ni][0] *= al0; oacc[ni][1] *= al0;
            oacc[ni][2] *= al1; oacc[ni][3] *= al1;
        }

        #pragma unroll
        for (int ni = 0; ni < 8; ni++) {
            Ps[qr    ][ni * 8 + 2 * t]     = to_tf32(s[ni][0]);
            Ps[qr    ][ni * 8 + 2 * t + 1] = to_tf32(s[ni][1]);
            Ps[qr + 8][ni * 8 + 2 * t]     = to_tf32(s[ni][2]);
            Ps[qr + 8][ni * 8 + 2 * t + 1] = to_tf32(s[ni][3]);
        }
        __syncwarp();

        #pragma unroll
        for (int kk = 0; kk < 8; kk++) {
            float a[4];
            a[0] = Ps[qr    ][kk * 8 + t];
            a[1] = Ps[qr + 8][kk * 8 + t];
            a[2] = Ps[qr    ][kk * 8 + t + 4];
            a[3] = Ps[qr + 8][kk * 8 + t + 4];
            #pragma unroll
            for (int ni = 0; ni < 8; ni++) {
                float bf[2];
                bf[0] = Vs[kk * 8 + t    ][ni * 8 + g];
                bf[1] = Vs[kk * 8 + t + 4][ni * 8 + g];
                mma8(oacc[ni], a, bf);
            }
        }
    }

    const float inv0 = 1.f / l_run[0], inv1 = 1.f / l_run[1];
    const int r0 = q0 + warp * 16 + g;
    #pragma unroll
    for (int ni = 0; ni < 8; ni++) {
        const int col = hoff + ni * 8 + 2 * t;
        const __nv_bfloat162 p0 = __floats2bfloat162_rn(oacc[ni][0] * inv0, oacc[ni][1] * inv0);
        const __nv_bfloat162 p1 = __floats2bfloat162_rn(oacc[ni][2] * inv1, oacc[ni][3] * inv1);
        *(__nv_bfloat162*)(attn_out + (rowbase + r0) * 1024 + col)     = p0;
        *(__nv_bfloat162*)(attn_out + (rowbase + r0 + 8) * 1024 + col) = p1;
    }
}

// ---------------- host ----------------
extern "C" void kernel_launch(void* const* d_in, const int* in_sizes, int n_in,
                              void* d_out, int out_size)
{
    (void)in_sizes; (void)n_in; (void)out_size;
    const float* x    = (const float*)d_in[0];
    const int*   kvl  = (const int*)  d_in[1];
    const float* Wq   = (const float*)d_in[2];
    const float* bq   = (const float*)d_in[3];
    const float* Wkv  = (const float*)d_in[4];
    const float* bkv  = (const float*)d_in[5];
    const float* Wo   = (const float*)d_in[6];
    const float* bo   = (const float*)d_in[7];
    const float* ln_g = (const float*)d_in[8];
    const float* ln_b = (const float*)d_in[9];
    float* out = (float*)d_out;

    __nv_bfloat16 *xnb, *attnb, *wqkvb, *wob;
    float *qkv;
    cudaGetSymbolAddress((void**)&xnb,   g_xnb);
    cudaGetSymbolAddress((void**)&qkv,   g_qkv);
    cudaGetSymbolAddress((void**)&attnb, g_attnb);
    cudaGetSymbolAddress((void**)&wqkvb, g_wqkvb);
    cudaGetSymbolAddress((void**)&wob,   g_wob);

    cudaFuncSetAttribute(attn_kernel, cudaFuncAttributeMaxDynamicSharedMemorySize, ATTN_SMEM);
    cudaFuncSetAttribute(gemm_bf16_kernel, cudaFuncAttributeMaxDynamicSharedMemorySize, GEMM_SMEM);

    // 1) layernorm (bf16 out) + weight pack/round (bf16)
    ln_kernel<<<M_, 256>>>(x, ln_g, ln_b, xnb);
    round_w_kernel<<<4096, 256>>>(Wq, Wkv, Wo, wqkvb, wob);

    // 2) fused Q+KV projection: C[8192, 3072] fp32 (ldc 3072)
    gemm_bf16_kernel<<<dim3(3072 / GBN, M_ / GBM), 256, GEMM_SMEM>>>(
        xnb, wqkvb, bq, bkv, 1024, nullptr, qkv, 3072);

    // 3) flash attention (fp32 in, bf16 out)
    attn_kernel<<<dim3(S_ / 64, H_, B_), 128, ATTN_SMEM>>>(qkv, kvl, attnb);

    // 4) output projection + bias + residual (fp32 out)
    gemm_bf16_kernel<<<dim3(1024 / GBN, M_ / GBM), 256, GEMM_SMEM>>>(
        attnb, wob, bo, bo, 1 << 30, x, out, 1024);
}

// round 14
// speedup vs baseline: 1.0017x; 1.0011x over previous
#include <cuda_runtime.h>
#include <cuda_bf16.h>
#include <cstdint>

#define B_  4
#define S_  2048
#define D_  1024
#define H_  16
#define DH_ 64
#define M_  (B_ * S_)   // 8192

// ---------------- scratch (allocation-free: device globals) ----------------
__device__ __nv_bfloat16 g_xnb  [M_ * D_];      // 16 MB, bf16 LN output
__device__ float         g_qkv  [M_ * 3 * D_];  // 96 MB fp32 (Q|K|V)
__device__ __nv_bfloat16 g_attnb[M_ * D_];      // 16 MB, bf16 attention output
__device__ __nv_bfloat16 g_wqkvb[3 * D_ * D_];  // 6 MB, bf16 [Wq;Wkv] (3072x1024 K-major)
__device__ __nv_bfloat16 g_wob  [D_ * D_];      // 2 MB, bf16 Wo

// ---------------- helpers ----------------
__device__ __forceinline__ float to_tf32(float x) {
    uint32_t u;
    asm("cvt.rna.tf32.f32 %0, %1;" : "=r"(u) : "f"(x));
    return __uint_as_float(u);
}

__device__ __forceinline__ uint32_t smem_u32(const void* p) {
    uint32_t a;
    asm("{ .reg .u64 t; cvta.to.shared.u64 t, %1; cvt.u32.u64 %0, t; }" : "=r"(a) : "l"(p));
    return a;
}

__device__ __forceinline__ void cp16(uint32_t dst, const void* src) {
    asm volatile("cp.async.cg.shared.global [%0], [%1], 16;" :: "r"(dst), "l"(src) : "memory");
}

__device__ __forceinline__ void ldsm4(uint32_t& r0, uint32_t& r1, uint32_t& r2, uint32_t& r3,
                                      uint32_t addr) {
    asm volatile("ldmatrix.sync.aligned.m8n8.x4.shared.b16 {%0,%1,%2,%3}, [%4];"
                 : "=r"(r0), "=r"(r1), "=r"(r2), "=r"(r3) : "r"(addr));
}

// D += A(16x16) * B(16x8), bf16 in / f32 accumulate
__device__ __forceinline__ void mma16(float* d, const uint32_t* a, uint32_t b0, uint32_t b1) {
    asm volatile(
        "mma.sync.aligned.m16n8k16.row.col.f32.bf16.bf16.f32 "
        "{%0,%1,%2,%3}, {%4,%5,%6,%7}, {%8,%9}, {%0,%1,%2,%3};\n"
        : "+f"(d[0]), "+f"(d[1]), "+f"(d[2]), "+f"(d[3])
        : "r"(a[0]), "r"(a[1]), "r"(a[2]), "r"(a[3]), "r"(b0), "r"(b1));
}

// legacy tf32 mma for the attention kernel (unchanged)
__device__ __forceinline__ void mma8(float* d, const float* a, const float* b) {
    asm volatile(
        "mma.sync.aligned.m16n8k8.row.col.f32.tf32.tf32.f32 "
        "{%0,%1,%2,%3}, {%4,%5,%6,%7}, {%8,%9}, {%0,%1,%2,%3};\n"
        : "+f"(d[0]), "+f"(d[1]), "+f"(d[2]), "+f"(d[3])
        : "r"(__float_as_uint(a[0])), "r"(__float_as_uint(a[1])),
          "r"(__float_as_uint(a[2])), "r"(__float_as_uint(a[3])),
          "r"(__float_as_uint(b[0])), "r"(__float_as_uint(b[1])));
}

// ---------------- kernel 1: LayerNorm (writes bf16 xn) ----------------
__global__ void __launch_bounds__(256) ln_kernel(
    const float* __restrict__ x, const float* __restrict__ gw,
    const float* __restrict__ bw, __nv_bfloat16* __restrict__ out)
{
    __shared__ float red0[8], red1[8];
    const int row = blockIdx.x;
    const int tid = threadIdx.x;
    const float4 v = ((const float4*)(x + (size_t)row * D_))[tid];

    float s  = v.x + v.y + v.z + v.w;
    float s2 = v.x*v.x + v.y*v.y + v.z*v.z + v.w*v.w;
    #pragma unroll
    for (int o = 16; o; o >>= 1) {
        s  += __shfl_xor_sync(0xffffffffu, s,  o);
        s2 += __shfl_xor_sync(0xffffffffu, s2, o);
    }
    if ((tid & 31) == 0) { red0[tid >> 5] = s; red1[tid >> 5] = s2; }
    __syncthreads();
    s = 0.f; s2 = 0.f;
    #pragma unroll
    for (int i = 0; i < 8; i++) { s += red0[i]; s2 += red1[i]; }

    const float mu  = s * (1.0f / D_);
    float var = s2 * (1.0f / D_) - mu * mu;
    if (var < 0.f) var = 0.f;
    const float r = rsqrtf(var + 1e-5f);

    const float4 g4 = ((const float4*)gw)[tid];
    const float4 b4 = ((const float4*)bw)[tid];
    const __nv_bfloat162 p0 = __floats2bfloat162_rn((v.x - mu) * r * g4.x + b4.x,
                                                    (v.y - mu) * r * g4.y + b4.y);
    const __nv_bfloat162 p1 = __floats2bfloat162_rn((v.z - mu) * r * g4.z + b4.z,
                                                    (v.w - mu) * r * g4.w + b4.w);
    uint2 pk;
    pk.x = *(const uint32_t*)&p0;
    pk.y = *(const uint32_t*)&p1;
    ((uint2*)(out + (size_t)row * D_))[tid] = pk;
}

// ---------------- kernel 1b: pack + round weights to bf16 ----------------
__global__ void __launch_bounds__(256) round_w_kernel(
    const float* __restrict__ Wq, const float* __restrict__ Wkv,
    const float* __restrict__ Wo, __nv_bfloat16* __restrict__ wqkv,
    __nv_bfloat16* __restrict__ wo)
{
    const int i = blockIdx.x * 256 + threadIdx.x;     // float4 index; grid covers 1M
    const int QKV4 = 3 * 1024 * 1024 / 4;             // 786432
    const int Q4   = 1024 * 1024 / 4;                 // 262144
    float4 v;
    __nv_bfloat16* dst;
    int j;
    if (i < QKV4) {
        v = (i < Q4) ? ((const float4*)Wq)[i] : ((const float4*)Wkv)[i - Q4];
        dst = wqkv; j = i;
    } else {
        j = i - QKV4;
        v = ((const float4*)Wo)[j];
        dst = wo;
    }
    const __nv_bfloat162 p0 = __floats2bfloat162_rn(v.x, v.y);
    const __nv_bfloat162 p1 = __floats2bfloat162_rn(v.z, v.w);
    uint2 pk;
    pk.x = *(const uint32_t*)&p0;
    pk.y = *(const uint32_t*)&p1;
    ((uint2*)dst)[j] = pk;
}

// ---------------- kernel 2/4: bf16 mma.m16n8k16 + ldmatrix GEMM ----------------
// C[m,n] = sum_k A[m,k]*W[n,k] + bias[n] (+resid[m,n]);  K = 1024 fixed.
// BM=128, BN=128, BK=32, 4-stage cp.async. 8 warps (2x4), warp tile 64x32.
#define GBM 128
#define GBN 128
#define GBK 32
#define GNT (1024 / GBK)              // 32 k-tiles
#define GROWB 80                      // padded row bytes (32 bf16 = 64B + 16B pad)
#define TILE_BYTES (128 * GROWB)      // 10240 per operand
#define STG_BYTES  (2 * TILE_BYTES)   // 20480 (A then B)
#define GEMM_SMEM  (4 * STG_BYTES)    // 81920 B

__device__ __forceinline__ void g_load_tile(
    uint32_t smb, int stage, int tid,
    const __nv_bfloat16* __restrict__ A, const __nv_bfloat16* __restrict__ W,
    int bm, int k0)
{
    const uint32_t sa = smb + stage * STG_BYTES;
    const uint32_t sb = sa + TILE_BYTES;
    #pragma unroll
    for (int i = 0; i < 2; i++) {
        const int idx = tid + i * 256;
        const int r = idx >> 2, ch = idx & 3;                 // 4 x 16B chunks per 64B row
        cp16(sa + (uint32_t)(r * GROWB + ch * 16), A + (size_t)(bm + r) * 1024 + k0 + ch * 8);
    }
    #pragma unroll
    for (int i = 0; i < 2; i++) {
        const int idx = tid + i * 256;
        const int r = idx >> 2, ch = idx & 3;
        cp16(sb + (uint32_t)(r * GROWB + ch * 16), W + (size_t)r * 1024 + k0 + ch * 8);
    }
}

__global__ void __launch_bounds__(256, 2) gemm_bf16_kernel(
    const __nv_bfloat16* __restrict__ A, const __nv_bfloat16* __restrict__ W,
    const float* __restrict__ bias0, const float* __restrict__ bias1, int bsplit,
    const float* __restrict__ resid, float* __restrict__ C, int ldc)
{
    extern __shared__ char smc[];
    const uint32_t smb = smem_u32(smc);
    const int tid  = threadIdx.x;
    const int warp = tid >> 5, lane = tid & 31;
    const int g = lane >> 2, tl = lane & 3;
    const int lr = lane & 7, lm = lane >> 3;     // ldmatrix row / matrix id
    const int bm = blockIdx.y * GBM;
    const int n0 = blockIdx.x * GBN;
    const int wm = (warp >> 2) << 6;   // 0 or 64
    const int wn = (warp & 3) << 5;    // 0,32,64,96
    const __nv_bfloat16* Wt = W + (size_t)n0 * 1024;
    const float* bias = (n0 < bsplit) ? bias0 + n0 : bias1 + (n0 - bsplit);

    float acc[4][4][4] = {};

    // prologue: stages 0..2
    g_load_tile(smb, 0, tid, A, Wt, bm, 0);
    asm volatile("cp.async.commit_group;" ::: "memory");
    g_load_tile(smb, 1, tid, A, Wt, bm, GBK);
    asm volatile("cp.async.commit_group;" ::: "memory");
    g_load_tile(smb, 2, tid, A, Wt, bm, 2 * GBK);
    asm volatile("cp.async.commit_group;" ::: "memory");

    // precomputed ldmatrix lane offsets
    const uint32_t a_lane_off = (uint32_t)(((lm & 1) * 8 + lr) * GROWB + ((lm >> 1) * 8) * 2);
    const uint32_t b_lane_off = (uint32_t)(((lm >> 1) * 8 + lr) * GROWB + ((lm & 1) * 8) * 2);

    #pragma unroll 1
    for (int t = 0; t < GNT; ++t) {
        asm volatile("cp.async.wait_group 2;" ::: "memory");   // tile t resident
        __syncthreads();                                        // stage (t+3)&3 fully consumed

        const int u = t + 3;
        if (u < GNT) g_load_tile(smb, u & 3, tid, A, Wt, bm, u * GBK);
        asm volatile("cp.async.commit_group;" ::: "memory");

        const uint32_t sA = smb + (t & 3) * STG_BYTES;
        const uint32_t sB = sA + TILE_BYTES;

        #pragma unroll
        for (int kk = 0; kk < GBK; kk += 16) {
            uint32_t a[4][4];
            #pragma unroll
            for (int mi = 0; mi < 4; mi++) {
                const uint32_t addr = sA + (uint32_t)((wm + mi * 16) * GROWB + kk * 2) + a_lane_off;
                ldsm4(a[mi][0], a[mi][1], a[mi][2], a[mi][3], addr);
            }
            #pragma unroll
            for (int nb = 0; nb < 2; nb++) {
                uint32_t b0, b1, b2, b3;
                const uint32_t addr = sB + (uint32_t)((wn + nb * 16) * GROWB + kk * 2) + b_lane_off;
                ldsm4(b0, b1, b2, b3, addr);
                #pragma unroll
                for (int mi = 0; mi < 4; mi++) {
                    mma16(acc[mi][2 * nb],     a[mi], b0, b1);
                    mma16(acc[mi][2 * nb + 1], a[mi], b2, b3);
                }
            }
        }
    }

    // epilogue: bias (+resid), float2 stores
    #pragma unroll
    for (int mi = 0; mi < 4; mi++) {
        const int r0 = bm + wm + mi * 16 + g;
        #pragma unroll
        for (int ni = 0; ni < 4; ni++) {
            const int cl = wn + ni * 8 + 2 * tl;
            const int col = n0 + cl;
            const float bb0 = bias[cl], bb1 = bias[cl + 1];
            float v0 = acc[mi][ni][0] + bb0, v1 = acc[mi][ni][1] + bb1;
            float v2 = acc[mi][ni][2] + bb0, v3 = acc[mi][ni][3] + bb1;
            if (resid) {
                const float2 ra = *(const float2*)(resid + (size_t)r0 * ldc + col);
                const float2 rb = *(const float2*)(resid + (size_t)(r0 + 8) * ldc + col);
                v0 += ra.x; v1 += ra.y; v2 += rb.x; v3 += rb.y;
            }
            *(float2*)(C + (size_t)r0 * ldc + col)       = make_float2(v0, v1);
            *(float2*)(C + (size_t)(r0 + 8) * ldc + col) = make_float2(v2, v3);
        }
    }
}

// ---------------- kernel 3: flash attention (tf32; bf16 output) ----------------
#define AT_STR 68
#define ATTN_SMEM (4 * 64 * AT_STR * 4)   // 69632 B

__global__ void __launch_bounds__(128) attn_kernel(
    const float* __restrict__ qkv, const int* __restrict__ kvlens,
    __nv_bfloat16* __restrict__ attn_out)
{
    extern __shared__ float sma[];
    float (*Qs)[AT_STR] = (float(*)[AT_STR])(sma);
    float (*Ks)[AT_STR] = (float(*)[AT_STR])(sma + 64 * AT_STR);
    float (*Vs)[AT_STR] = (float(*)[AT_STR])(sma + 2 * 64 * AT_STR);
    float (*Ps)[AT_STR] = (float(*)[AT_STR])(sma + 3 * 64 * AT_STR);

    const int qt = blockIdx.x, h = blockIdx.y, b = blockIdx.z;
    const int q0 = qt * 64;
    const int kvlen = kvlens[b];
    const int tid = threadIdx.x, warp = tid >> 5, lane = tid & 31;
    const int g = lane >> 2, t = lane & 3;
    const size_t rowbase = (size_t)b * S_;
    const int hoff = h * DH_;

    #pragma unroll
    for (int i = 0; i < 8; i++) {
        const int idx = tid + i * 128;
        const int r = idx >> 4, c = (idx & 15) << 2;
        const float4 v = *(const float4*)(qkv + (rowbase + q0 + r) * 3072 + hoff + c);
        Qs[r][c + 0] = to_tf32(v.x); Qs[r][c + 1] = to_tf32(v.y);
        Qs[r][c + 2] = to_tf32(v.z); Qs[r][c + 3] = to_tf32(v.w);
    }

    float m_run[2] = { -1e30f, -1e30f };
    float l_run[2] = { 0.f, 0.f };
    float oacc[8][4] = {};

    int kmax = (kvlen - 1) >> 6;
    const int kt_end = (qt < kmax) ? qt : kmax;

    for (int kt = 0; kt <= kt_end; kt++) {
        const int k0 = kt * 64;
        __syncthreads();
        #pragma unroll
        for (int i = 0; i < 8; i++) {
            const int idx = tid + i * 128;
            const int r = idx >> 4, c = (idx & 15) << 2;
            const float4 kv4 = *(const float4*)(qkv + (rowbase + k0 + r) * 3072 + 1024 + hoff + c);
            Ks[r][c + 0] = to_tf32(kv4.x); Ks[r][c + 1] = to_tf32(kv4.y);
            Ks[r][c + 2] = to_tf32(kv4.z); Ks[r][c + 3] = to_tf32(kv4.w);
            const float4 vv4 = *(const float4*)(qkv + (rowbase + k0 + r) * 3072 + 2048 + hoff + c);
            Vs[r][c + 0] = to_tf32(vv4.x); Vs[r][c + 1] = to_tf32(vv4.y);
            Vs[r][c + 2] = to_tf32(vv4.z); Vs[r][c + 3] = to_tf32(vv4.w);
        }
        __syncthreads();

        float s[8][4] = {};
        const int qr = warp * 16 + g;
        #pragma unroll
        for (int kk = 0; kk < 8; kk++) {
            float a[4];
            a[0] = Qs[qr    ][kk * 8 + t];
            a[1] = Qs[qr + 8][kk * 8 + t];
            a[2] = Qs[qr    ][kk * 8 + t + 4];
            a[3] = Qs[qr + 8][kk * 8 + t + 4];
            #pragma unroll
            for (int ni = 0; ni < 8; ni++) {
                float bf[2];
                bf[0] = Ks[ni * 8 + g][kk * 8 + t];
                bf[1] = Ks[ni * 8 + g][kk * 8 + t + 4];
                mma8(s[ni], a, bf);
            }
        }

        const int qrow0 = q0 + qr, qrow1 = qrow0 + 8;
        #pragma unroll
        for (int ni = 0; ni < 8; ni++) {
            const int c0 = k0 + ni * 8 + 2 * t, c1 = c0 + 1;
            s[ni][0] = (c0 <= qrow0 && c0 < kvlen) ? s[ni][0] * 0.125f : -1e30f;
            s[ni][1] = (c1 <= qrow0 && c1 < kvlen) ? s[ni][1] * 0.125f : -1e30f;
            s[ni][2] = (c0 <= qrow1 && c0 < kvlen) ? s[ni][2] * 0.125f : -1e30f;
            s[ni][3] = (c1 <= qrow1 && c1 < kvlen) ? s[ni][3] * 0.125f : -1e30f;
        }

        float mx0 = -1e30f, mx1 = -1e30f;
        #pragma unroll
        for (int ni = 0; ni < 8; ni++) {
            mx0 = fmaxf(mx0, fmaxf(s[ni][0], s[ni][1]));
            mx1 = fmaxf(mx1, fmaxf(s[ni][2], s[ni][3]));
        }
        mx0 = fmaxf(mx0, __shfl_xor_sync(0xffffffffu, mx0, 1));
        mx0 = fmaxf(mx0, __shfl_xor_sync(0xffffffffu, mx0, 2));
        mx1 = fmaxf(mx1, __shfl_xor_sync(0xffffffffu, mx1, 1));
        mx1 = fmaxf(mx1, __shfl_xor_sync(0xffffffffu, mx1, 2));

        const float mn0 = fmaxf(m_run[0], mx0), mn1 = fmaxf(m_run[1], mx1);
        const float al0 = __expf(m_run[0] - mn0), al1 = __expf(m_run[1] - mn1);

        float rs0 = 0.f, rs1 = 0.f;
        #pragma unroll
        for (int ni = 0; ni < 8; ni++) {
            s[ni][0] = __expf(s[ni][0] - mn0); s[ni][1] = __expf(s[ni][1] - mn0);
            s[ni][2] = __expf(s[ni][2] - mn1); s[ni][3] = __expf(s[ni][3] - mn1);
            rs0 += s[ni][0] + s[ni][1];
            rs1 += s[ni][2] + s[ni][3];
        }
        rs0 += __shfl_xor_sync(0xffffffffu, rs0, 1);
        rs0 += __shfl_xor_sync(0xffffffffu, rs0, 2);
        rs1 += __shfl_xor_sync(0xffffffffu, rs1, 1);
        rs1 += __shfl_xor_sync(0xffffffffu, rs1, 2);

        l_run[0] = l_run[0] * al0 + rs0;
        l_run[1] = l_run[1] * al1 + rs1;
        m_run[0] = mn0; m_run[1] = mn1;

        #pragma unroll
        for (int ni = 0; ni < 8; ni++) {
            oacc[ni][0] *= al0; oacc[ni][1] *= al0;
            oacc[ni][2] *= al1; oacc[ni][3] *= al1;
        }

        #pragma unroll
        for (int ni = 0; ni < 8; ni++) {
            Ps[qr    ][ni * 8 + 2 * t]     = to_tf32(s[ni][0]);
            Ps[qr    ][ni * 8 + 2 * t + 1] = to_tf32(s[ni][1]);
            Ps[qr + 8][ni * 8 + 2 * t]     = to_tf32(s[ni][2]);
            Ps[qr + 8][ni * 8 + 2 * t + 1] = to_tf32(s[ni][3]);
        }
        __syncwarp();

        #pragma unroll
        for (int kk = 0; kk < 8; kk++) {
            float a[4];
            a[0] = Ps[qr    ][kk * 8 + t];
            a[1] = Ps[qr + 8][kk * 8 + t];
            a[2] = Ps[qr    ][kk * 8 + t + 4];
            a[3] = Ps[qr + 8][kk * 8 + t + 4];
            #pragma unroll
            for (int ni = 0; ni < 8; ni++) {
                float bf[2];
                bf[0] = Vs[kk * 8 + t    ][ni * 8 + g];
                bf[1] = Vs[kk * 8 + t + 4][ni * 8 + g];
                mma8(oacc[ni], a, bf);
            }
        }
    }

    const float inv0 = 1.f / l_run[0], inv1 = 1.f / l_run[1];
    const int r0 = q0 + warp * 16 + g;
    #pragma unroll
    for (int ni = 0; ni < 8; ni++) {
        const int col = hoff + ni * 8 + 2 * t;
        const __nv_bfloat162 p0 = __floats2bfloat162_rn(oacc[ni][0] * inv0, oacc[ni][1] * inv0);
        const __nv_bfloat162 p1 = __floats2bfloat162_rn(oacc[ni][2] * inv1, oacc[ni][3] * inv1);
        *(__nv_bfloat162*)(attn_out + (rowbase + r0) * 1024 + col)     = p0;
        *(__nv_bfloat162*)(attn_out + (rowbase + r0 + 8) * 1024 + col) = p1;
    }
}

// ---------------- host ----------------
extern "C" void kernel_launch(void* const* d_in, const int* in_sizes, int n_in,
                              void* d_out, int out_size)
{
    (void)in_sizes; (void)n_in; (void)out_size;
    const float* x    = (const float*)d_in[0];
    const int*   kvl  = (const int*)  d_in[1];
    const float* Wq   = (const float*)d_in[2];
    const float* bq   = (const float*)d_in[3];
    const float* Wkv  = (const float*)d_in[4];
    const float* bkv  = (const float*)d_in[5];
    const float* Wo   = (const float*)d_in[6];
    const float* bo   = (const float*)d_in[7];
    const float* ln_g = (const float*)d_in[8];
    const float* ln_b = (const float*)d_in[9];
    float* out = (float*)d_out;

    __nv_bfloat16 *xnb, *attnb, *wqkvb, *wob;
    float *qkv;
    cudaGetSymbolAddress((void**)&xnb,   g_xnb);
    cudaGetSymbolAddress((void**)&qkv,   g_qkv);
    cudaGetSymbolAddress((void**)&attnb, g_attnb);
    cudaGetSymbolAddress((void**)&wqkvb, g_wqkvb);
    cudaGetSymbolAddress((void**)&wob,   g_wob);

    cudaFuncSetAttribute(attn_kernel, cudaFuncAttributeMaxDynamicSharedMemorySize, ATTN_SMEM);
    cudaFuncSetAttribute(gemm_bf16_kernel, cudaFuncAttributeMaxDynamicSharedMemorySize, GEMM_SMEM);

    // 1) layernorm (bf16 out) + weight pack/round (bf16)
    ln_kernel<<<M_, 256>>>(x, ln_g, ln_b, xnb);
    round_w_kernel<<<4096, 256>>>(Wq, Wkv, Wo, wqkvb, wob);

    // 2) fused Q+KV projection: C[8192, 3072] fp32 (ldc 3072)
    gemm_bf16_kernel<<<dim3(3072 / GBN, M_ / GBM), 256, GEMM_SMEM>>>(
        xnb, wqkvb, bq, bkv, 1024, nullptr, qkv, 3072);

    // 3) flash attention (fp32 in, bf16 out)
    attn_kernel<<<dim3(S_ / 64, H_, B_), 128, ATTN_SMEM>>>(qkv, kvl, attnb);

    // 4) output projection + bias + residual (fp32 out)
    gemm_bf16_kernel<<<dim3(1024 / GBN, M_ / GBM), 256, GEMM_SMEM>>>(
        attnb, wob, bo, bo, 1 << 30, x, out, 1024);
}

// round 15
// speedup vs baseline: 1.5338x; 1.5312x over previous
#include <cuda_runtime.h>
#include <cuda_fp16.h>
#include <cstdint>

#define B_  4
#define S_  2048
#define D_  1024
#define H_  16
#define DH_ 64
#define M_  (B_ * S_)   // 8192

// Q prescale folded into GEMM1 epilogue: 1/sqrt(DH) * log2(e)
#define QSCALE (0.125f * 1.44269504088896340736f)

// ---------------- scratch (allocation-free: device globals) ----------------
__device__ __half g_xnh  [M_ * D_];      // 16 MB, fp16 LN output
__device__ __half g_qkv  [M_ * 3 * D_];  // 48 MB fp16 (Q*qscale | K | V)
__device__ __half g_attnh[M_ * D_];      // 16 MB, fp16 attention output
__device__ __half g_wqkvh[3 * D_ * D_];  // 6 MB, fp16 [Wq;Wkv] (3072x1024 K-major)
__device__ __half g_woh  [D_ * D_];      // 2 MB, fp16 Wo

// ---------------- helpers ----------------
__device__ __forceinline__ uint32_t smem_u32(const void* p) {
    uint32_t a;
    asm("{ .reg .u64 t; cvta.to.shared.u64 t, %1; cvt.u32.u64 %0, t; }" : "=r"(a) : "l"(p));
    return a;
}

__device__ __forceinline__ void cp16(uint32_t dst, const void* src) {
    asm volatile("cp.async.cg.shared.global [%0], [%1], 16;" :: "r"(dst), "l"(src) : "memory");
}

__device__ __forceinline__ void ldsm4(uint32_t& r0, uint32_t& r1, uint32_t& r2, uint32_t& r3,
                                      uint32_t addr) {
    asm volatile("ldmatrix.sync.aligned.m8n8.x4.shared.b16 {%0,%1,%2,%3}, [%4];"
                 : "=r"(r0), "=r"(r1), "=r"(r2), "=r"(r3) : "r"(addr));
}

__device__ __forceinline__ void ldsm4t(uint32_t& r0, uint32_t& r1, uint32_t& r2, uint32_t& r3,
                                       uint32_t addr) {
    asm volatile("ldmatrix.sync.aligned.m8n8.x4.trans.shared.b16 {%0,%1,%2,%3}, [%4];"
                 : "=r"(r0), "=r"(r1), "=r"(r2), "=r"(r3) : "r"(addr));
}

// D += A(16x16) * B(16x8), fp16 in / f32 accumulate
__device__ __forceinline__ void mma16h(float* d, const uint32_t* a, uint32_t b0, uint32_t b1) {
    asm volatile(
        "mma.sync.aligned.m16n8k16.row.col.f32.f16.f16.f32 "
        "{%0,%1,%2,%3}, {%4,%5,%6,%7}, {%8,%9}, {%0,%1,%2,%3};\n"
        : "+f"(d[0]), "+f"(d[1]), "+f"(d[2]), "+f"(d[3])
        : "r"(a[0]), "r"(a[1]), "r"(a[2]), "r"(a[3]), "r"(b0), "r"(b1));
}

__device__ __forceinline__ uint32_t ph2(float x, float y) {
    const __half2 h = __floats2half2_rn(x, y);
    return *(const uint32_t*)&h;
}

__device__ __forceinline__ float fexp2(float x) {
    float y;
    asm("ex2.approx.ftz.f32 %0, %1;" : "=f"(y) : "f"(x));
    return y;
}

// ---------------- kernel 1: LayerNorm (writes fp16 xn) ----------------
__global__ void __launch_bounds__(256) ln_kernel(
    const float* __restrict__ x, const float* __restrict__ gw,
    const float* __restrict__ bw, __half* __restrict__ out)
{
    __shared__ float red0[8], red1[8];
    const int row = blockIdx.x;
    const int tid = threadIdx.x;
    const float4 v = ((const float4*)(x + (size_t)row * D_))[tid];

    float s  = v.x + v.y + v.z + v.w;
    float s2 = v.x*v.x + v.y*v.y + v.z*v.z + v.w*v.w;
    #pragma unroll
    for (int o = 16; o; o >>= 1) {
        s  += __shfl_xor_sync(0xffffffffu, s,  o);
        s2 += __shfl_xor_sync(0xffffffffu, s2, o);
    }
    if ((tid & 31) == 0) { red0[tid >> 5] = s; red1[tid >> 5] = s2; }
    __syncthreads();
    s = 0.f; s2 = 0.f;
    #pragma unroll
    for (int i = 0; i < 8; i++) { s += red0[i]; s2 += red1[i]; }

    const float mu  = s * (1.0f / D_);
    float var = s2 * (1.0f / D_) - mu * mu;
    if (var < 0.f) var = 0.f;
    const float r = rsqrtf(var + 1e-5f);

    const float4 g4 = ((const float4*)gw)[tid];
    const float4 b4 = ((const float4*)bw)[tid];
    uint2 pk;
    pk.x = ph2((v.x - mu) * r * g4.x + b4.x, (v.y - mu) * r * g4.y + b4.y);
    pk.y = ph2((v.z - mu) * r * g4.z + b4.z, (v.w - mu) * r * g4.w + b4.w);
    ((uint2*)(out + (size_t)row * D_))[tid] = pk;
}

// ---------------- kernel 1b: pack + round weights to fp16 ----------------
__global__ void __launch_bounds__(256) round_w_kernel(
    const float* __restrict__ Wq, const float* __restrict__ Wkv,
    const float* __restrict__ Wo, __half* __restrict__ wqkv,
    __half* __restrict__ wo)
{
    const int i = blockIdx.x * 256 + threadIdx.x;     // float4 index; grid covers 1M
    const int QKV4 = 3 * 1024 * 1024 / 4;             // 786432
    const int Q4   = 1024 * 1024 / 4;                 // 262144
    float4 v;
    __half* dst;
    int j;
    if (i < QKV4) {
        v = (i < Q4) ? ((const float4*)Wq)[i] : ((const float4*)Wkv)[i - Q4];
        dst = wqkv; j = i;
    } else {
        j = i - QKV4;
        v = ((const float4*)Wo)[j];
        dst = wo;
    }
    uint2 pk;
    pk.x = ph2(v.x, v.y);
    pk.y = ph2(v.z, v.w);
    ((uint2*)dst)[j] = pk;
}

// ---------------- kernel 2/4: fp16 mma.m16n8k16 + ldmatrix GEMM ----------------
// C[m,n] = sum_k A[m,k]*W[n,k] + bias[n] (+resid[m,n]);  K = 1024 fixed.
// BM=128, BN=128, BK=32, 4-stage cp.async. 8 warps (2x4), warp tile 64x32.
// HALF_OUT: C is fp16; cols < qcols additionally scaled by qscale (Q prescale).
#define GBM 128
#define GBN 128
#define GBK 32
#define GNT (1024 / GBK)              // 32 k-tiles
#define GROWB 80                      // padded row bytes (32 fp16 = 64B + 16B pad)
#define TILE_BYTES (128 * GROWB)      // 10240 per operand
#define STG_BYTES  (2 * TILE_BYTES)   // 20480 (A then B)
#define GEMM_SMEM  (4 * STG_BYTES)    // 81920 B

__device__ __forceinline__ void g_load_tile(
    uint32_t smb, int stage, int tid,
    const __half* __restrict__ A, const __half* __restrict__ W,
    int bm, int k0)
{
    const uint32_t sa = smb + stage * STG_BYTES;
    const uint32_t sb = sa + TILE_BYTES;
    #pragma unroll
    for (int i = 0; i < 2; i++) {
        const int idx = tid + i * 256;
        const int r = idx >> 2, ch = idx & 3;                 // 4 x 16B chunks per 64B row
        cp16(sa + (uint32_t)(r * GROWB + ch * 16), A + (size_t)(bm + r) * 1024 + k0 + ch * 8);
    }
    #pragma unroll
    for (int i = 0; i < 2; i++) {
        const int idx = tid + i * 256;
        const int r = idx >> 2, ch = idx & 3;
        cp16(sb + (uint32_t)(r * GROWB + ch * 16), W + (size_t)r * 1024 + k0 + ch * 8);
    }
}

template<bool HALF_OUT>
__global__ void __launch_bounds__(256, 2) gemm_h_kernel(
    const __half* __restrict__ A, const __half* __restrict__ W,
    const float* __restrict__ bias0, const float* __restrict__ bias1, int bsplit,
    const float* __restrict__ resid, void* __restrict__ Cv, int ldc,
    int qcols, float qscale)
{
    extern __shared__ char smc[];
    const uint32_t smb = smem_u32(smc);
    const int tid  = threadIdx.x;
    const int warp = tid >> 5, lane = tid & 31;
    const int g = lane >> 2, tl = lane & 3;
    const int lr = lane & 7, lm = lane >> 3;     // ldmatrix row / matrix id
    const int bm = blockIdx.y * GBM;
    const int n0 = blockIdx.x * GBN;
    const int wm = (warp >> 2) << 6;   // 0 or 64
    const int wn = (warp & 3) << 5;    // 0,32,64,96
    const __half* Wt = W + (size_t)n0 * 1024;
    const float* bias = (n0 < bsplit) ? bias0 + n0 : bias1 + (n0 - bsplit);

    float acc[4][4][4] = {};

    // prologue: stages 0..2
    g_load_tile(smb, 0, tid, A, Wt, bm, 0);
    asm volatile("cp.async.commit_group;" ::: "memory");
    g_load_tile(smb, 1, tid, A, Wt, bm, GBK);
    asm volatile("cp.async.commit_group;" ::: "memory");
    g_load_tile(smb, 2, tid, A, Wt, bm, 2 * GBK);
    asm volatile("cp.async.commit_group;" ::: "memory");

    // precomputed ldmatrix lane offsets
    const uint32_t a_lane_off = (uint32_t)(((lm & 1) * 8 + lr) * GROWB + ((lm >> 1) * 8) * 2);
    const uint32_t b_lane_off = (uint32_t)(((lm >> 1) * 8 + lr) * GROWB + ((lm & 1) * 8) * 2);

    #pragma unroll 1
    for (int t = 0; t < GNT; ++t) {
        asm volatile("cp.async.wait_group 2;" ::: "memory");   // tile t resident
        __syncthreads();                                        // stage (t+3)&3 fully consumed

        const int u = t + 3;
        if (u < GNT) g_load_tile(smb, u & 3, tid, A, Wt, bm, u * GBK);
        asm volatile("cp.async.commit_group;" ::: "memory");

        const uint32_t sA = smb + (t & 3) * STG_BYTES;
        const uint32_t sB = sA + TILE_BYTES;

        #pragma unroll
        for (int kk = 0; kk < GBK; kk += 16) {
            uint32_t a[4][4];
            #pragma unroll
            for (int mi = 0; mi < 4; mi++) {
                const uint32_t addr = sA + (uint32_t)((wm + mi * 16) * GROWB + kk * 2) + a_lane_off;
                ldsm4(a[mi][0], a[mi][1], a[mi][2], a[mi][3], addr);
            }
            #pragma unroll
            for (int nb = 0; nb < 2; nb++) {
                uint32_t b0, b1, b2, b3;
                const uint32_t addr = sB + (uint32_t)((wn + nb * 16) * GROWB + kk * 2) + b_lane_off;
                ldsm4(b0, b1, b2, b3, addr);
                #pragma unroll
                for (int mi = 0; mi < 4; mi++) {
                    mma16h(acc[mi][2 * nb],     a[mi], b0, b1);
                    mma16h(acc[mi][2 * nb + 1], a[mi], b2, b3);
                }
            }
        }
    }

    // epilogue
    #pragma unroll
    for (int mi = 0; mi < 4; mi++) {
        const int r0 = bm + wm + mi * 16 + g;
        #pragma unroll
        for (int ni = 0; ni < 4; ni++) {
            const int cl = wn + ni * 8 + 2 * tl;
            const int col = n0 + cl;
            const float bb0 = bias[cl], bb1 = bias[cl + 1];
            float v0 = acc[mi][ni][0] + bb0, v1 = acc[mi][ni][1] + bb1;
            float v2 = acc[mi][ni][2] + bb0, v3 = acc[mi][ni][3] + bb1;
            if (HALF_OUT) {
                const float sc = (col < qcols) ? qscale : 1.0f;
                __half* C = (__half*)Cv;
                *(uint32_t*)(C + (size_t)r0 * ldc + col)       = ph2(v0 * sc, v1 * sc);
                *(uint32_t*)(C + (size_t)(r0 + 8) * ldc + col) = ph2(v2 * sc, v3 * sc);
            } else {
                float* C = (float*)Cv;
                if (resid) {
                    const float2 ra = *(const float2*)(resid + (size_t)r0 * ldc + col);
                    const float2 rb = *(const float2*)(resid + (size_t)(r0 + 8) * ldc + col);
                    v0 += ra.x; v1 += ra.y; v2 += rb.x; v3 += rb.y;
                }
                *(float2*)(C + (size_t)r0 * ldc + col)       = make_float2(v0, v1);
                *(float2*)(C + (size_t)(r0 + 8) * ldc + col) = make_float2(v2, v3);
            }
        }
    }
}

// ---------------- kernel 3: flash attention (fp16 mma + ldmatrix) ----------------
// 1 block = (b, h, 64 q-rows); 4 warps, warp owns 16 q-rows.
// Q scores arrive pre-scaled by 0.125*log2e -> softmax in exp2 domain.
#define ATS 72                         // halves per smem row (144 B, ldsm conflict-free)
#define AQ_BYTES  (64 * ATS * 2)       // 9216
#define AKV_BYTES (64 * ATS * 2)       // 9216 per matrix
#define ATTN_SMEM (AQ_BYTES + 3 * 2 * AKV_BYTES)   // 64512

__device__ __forceinline__ void attn_load_kv(
    uint32_t smb, int st, int tid,
    const __half* __restrict__ qkv, size_t rowbase, int hoff, int k0)
{
    const uint32_t sK = smb + AQ_BYTES + (uint32_t)st * 2 * AKV_BYTES;
    const uint32_t sV = sK + AKV_BYTES;
    #pragma unroll
    for (int i = 0; i < 4; i++) {
        const int idx = tid + i * 128;
        const int r = idx >> 3, ch = idx & 7;
        cp16(sK + (uint32_t)(r * 144 + ch * 16),
             qkv + (rowbase + k0 + r) * 3072 + 1024 + hoff + ch * 8);
    }
    #pragma unroll
    for (int i = 0; i < 4; i++) {
        const int idx = tid + i * 128;
        const int r = idx >> 3, ch = idx & 7;
        cp16(sV + (uint32_t)(r * 144 + ch * 16),
             qkv + (rowbase + k0 + r) * 3072 + 2048 + hoff + ch * 8);
    }
}

__global__ void __launch_bounds__(128) attn_kernel(
    const __half* __restrict__ qkv, const int* __restrict__ kvlens,
    __half* __restrict__ attn_out)
{
    extern __shared__ char smc[];
    const uint32_t smb = smem_u32(smc);
    const uint32_t sQ = smb;

    const int qt = blockIdx.x, h = blockIdx.y, b = blockIdx.z;
    const int q0 = qt * 64;
    const int kvlen = kvlens[b];
    const int tid = threadIdx.x, warp = tid >> 5, lane = tid & 31;
    const int g = lane >> 2, tl = lane & 3;
    const int lr = lane & 7, lm = lane >> 3;
    const size_t rowbase = (size_t)b * S_;
    const int hoff = h * DH_;

    const int kmax = (kvlen - 1) >> 6;
    const int kt_end = (qt < kmax) ? qt : kmax;

    // prologue: group0 = Q + KV0, group1 = KV1 (or empty)
    #pragma unroll
    for (int i = 0; i < 4; i++) {
        const int idx = tid + i * 128;
        const int r = idx >> 3, ch = idx & 7;
        cp16(sQ + (uint32_t)(r * 144 + ch * 16),
             qkv + (rowbase + q0 + r) * 3072 + hoff + ch * 8);
    }
    attn_load_kv(smb, 0, tid, qkv, rowbase, hoff, 0);
    asm volatile("cp.async.commit_group;" ::: "memory");
    if (kt_end >= 1) attn_load_kv(smb, 1, tid, qkv, rowbase, hoff, 64);
    asm volatile("cp.async.commit_group;" ::: "memory");

    const uint32_t ro = (uint32_t)((lm & 1) * 8 + lr);   // ldsm row within 16-row group
    const uint32_t co = (uint32_t)((lm >> 1) * 16);      // ldsm byte-col offset

    uint32_t aQ[4][4];
    float m_run[2] = { -1e30f, -1e30f };
    float l_run[2] = { 0.f, 0.f };
    float oacc[8][4] = {};
    const int qr = warp * 16 + g;

    #pragma unroll 1
    for (int kt = 0; kt <= kt_end; kt++) {
        asm volatile("cp.async.wait_group 1;" ::: "memory");   // tile kt resident
        __syncthreads();                                        // stage (kt+2)%3 consumers done

        const int u = kt + 2;
        if (u <= kt_end) attn_load_kv(smb, u % 3, tid, qkv, rowbase, hoff, u * 64);
        asm volatile("cp.async.commit_group;" ::: "memory");

        if (kt == 0) {   // hoist Q fragments (loop-invariant)
            #pragma unroll
            for (int kk = 0; kk < 4; kk++)
                ldsm4(aQ[kk][0], aQ[kk][1], aQ[kk][2], aQ[kk][3],
                      sQ + (uint32_t)(warp * 16 + ro) * 144 + kk * 32 + co);
        }

        const uint32_t sK = smb + AQ_BYTES + (uint32_t)(kt % 3) * 2 * AKV_BYTES;
        const uint32_t sV = sK + AKV_BYTES;
        const int k0 = kt * 64;

        // S = Q @ K^T  (scores pre-scaled, log2 domain)
        float s[8][4] = {};
        #pragma unroll
        for (int kk = 0; kk < 4; kk++) {
            #pragma unroll
            for (int j = 0; j < 4; j++) {
                uint32_t r0, r1, r2, r3;
                ldsm4(r0, r1, r2, r3, sK + (uint32_t)(j * 16 + ro) * 144 + kk * 32 + co);
                mma16h(s[2 * j],     aQ[kk], r0, r2);
                mma16h(s[2 * j + 1], aQ[kk], r1, r3);
            }
        }

        // masking only on boundary tiles
        const int qrow0 = q0 + qr, qrow1 = qrow0 + 8;
        if (kt == qt || k0 + 64 > kvlen) {
            const int lim0 = (qrow0 < kvlen - 1) ? qrow0 : kvlen - 1;
            const int lim1 = (qrow1 < kvlen - 1) ? qrow1 : kvlen - 1;
            #pragma unroll
            for (int ni = 0; ni < 8; ni++) {
                const int c0 = k0 + ni * 8 + 2 * tl, c1 = c0 + 1;
                if (c0 > lim0) s[ni][0] = -1e30f;
                if (c1 > lim0) s[ni][1] = -1e30f;
                if (c0 > lim1) s[ni][2] = -1e30f;
                if (c1 > lim1) s[ni][3] = -1e30f;
            }
        }

        // online softmax (exp2 domain)
        float mx0 = -1e30f, mx1 = -1e30f;
        #pragma unroll
        for (int ni = 0; ni < 8; ni++) {
            mx0 = fmaxf(mx0, fmaxf(s[ni][0], s[ni][1]));
            mx1 = fmaxf(mx1, fmaxf(s[ni][2], s[ni][3]));
        }
        mx0 = fmaxf(mx0, __shfl_xor_sync(0xffffffffu, mx0, 1));
        mx0 = fmaxf(mx0, __shfl_xor_sync(0xffffffffu, mx0, 2));
        mx1 = fmaxf(mx1, __shfl_xor_sync(0xffffffffu, mx1, 1));
        mx1 = fmaxf(mx1, __shfl_xor_sync(0xffffffffu, mx1, 2));

        const float mn0 = fmaxf(m_run[0], mx0), mn1 = fmaxf(m_run[1], mx1);
        const float al0 = fexp2(m_run[0] - mn0), al1 = fexp2(m_run[1] - mn1);

        float rs0 = 0.f, rs1 = 0.f;
        #pragma unroll
        for (int ni = 0; ni < 8; ni++) {
            s[ni][0] = fexp2(s[ni][0] - mn0); s[ni][1] = fexp2(s[ni][1] - mn0);
            s[ni][2] = fexp2(s[ni][2] - mn1); s[ni][3] = fexp2(s[ni][3] - mn1);
            rs0 += s[ni][0] + s[ni][1];
            rs1 += s[ni][2] + s[ni][3];
        }
        rs0 += __shfl_xor_sync(0xffffffffu, rs0, 1);
        rs0 += __shfl_xor_sync(0xffffffffu, rs0, 2);
        rs1 += __shfl_xor_sync(0xffffffffu, rs1, 1);
        rs1 += __shfl_xor_sync(0xffffffffu, rs1, 2);

        l_run[0] = l_run[0] * al0 + rs0;
        l_run[1] = l_run[1] * al1 + rs1;
        m_run[0] = mn0; m_run[1] = mn1;

        #pragma unroll
        for (int ni = 0; ni < 8; ni++) {
            oacc[ni][0] *= al0; oacc[ni][1] *= al0;
            oacc[ni][2] *= al1; oacc[ni][3] *= al1;
        }

        // O += P @ V  (P: C-frag -> A-frag in registers, V via ldmatrix.trans)
        #pragma unroll
        for (int kk2 = 0; kk2 < 4; kk2++) {
            uint32_t a[4];
            a[0] = ph2(s[2 * kk2][0],     s[2 * kk2][1]);
            a[1] = ph2(s[2 * kk2][2],     s[2 * kk2][3]);
            a[2] = ph2(s[2 * kk2 + 1][0], s[2 * kk2 + 1][1]);
            a[3] = ph2(s[2 * kk2 + 1][2], s[2 * kk2 + 1][3]);
            #pragma unroll
            for (int jd = 0; jd < 4; jd++) {
                uint32_t r0, r1, r2, r3;
                ldsm4t(r0, r1, r2, r3, sV + (uint32_t)(kk2 * 16 + ro) * 144 + jd * 32 + co);
                mma16h(oacc[2 * jd],     a, r0, r1);
                mma16h(oacc[2 * jd + 1], a, r2, r3);
            }
        }
    }

    // finalize + store fp16
    const float inv0 = 1.f / l_run[0], inv1 = 1.f / l_run[1];
    const int r0 = q0 + qr;
    #pragma unroll
    for (int ni = 0; ni < 8; ni++) {
        const int col = hoff + ni * 8 + 2 * tl;
        *(uint32_t*)(attn_out + (rowbase + r0) * 1024 + col) =
            ph2(oacc[ni][0] * inv0, oacc[ni][1] * inv0);
        *(uint32_t*)(attn_out + (rowbase + r0 + 8) * 1024 + col) =
            ph2(oacc[ni][2] * inv1, oacc[ni][3] * inv1);
    }
}

// ---------------- host ----------------
extern "C" void kernel_launch(void* const* d_in, const int* in_sizes, int n_in,
                              void* d_out, int out_size)
{
    (void)in_sizes; (void)n_in; (void)out_size;
    const float* x    = (const float*)d_in[0];
    const int*   kvl  = (const int*)  d_in[1];
    const float* Wq   = (const float*)d_in[2];
    const float* bq   = (const float*)d_in[3];
    const float* Wkv  = (const float*)d_in[4];
    const float* bkv  = (const float*)d_in[5];
    const float* Wo   = (const float*)d_in[6];
    const float* bo   = (const float*)d_in[7];
    const float* ln_g = (const float*)d_in[8];
    const float* ln_b = (const float*)d_in[9];
    float* out = (float*)d_out;

    __half *xnh, *qkv, *attnh, *wqkvh, *woh;
    cudaGetSymbolAddress((void**)&xnh,   g_xnh);
    cudaGetSymbolAddress((void**)&qkv,   g_qkv);
    cudaGetSymbolAddress((void**)&attnh, g_attnh);
    cudaGetSymbolAddress((void**)&wqkvh, g_wqkvh);
    cudaGetSymbolAddress((void**)&woh,   g_woh);

    cudaFuncSetAttribute(attn_kernel, cudaFuncAttributeMaxDynamicSharedMemorySize, ATTN_SMEM);
    cudaFuncSetAttribute(gemm_h_kernel<true>,  cudaFuncAttributeMaxDynamicSharedMemorySize, GEMM_SMEM);
    cudaFuncSetAttribute(gemm_h_kernel<false>, cudaFuncAttributeMaxDynamicSharedMemorySize, GEMM_SMEM);

    // 1) layernorm (fp16 out) + weight pack/round (fp16)
    ln_kernel<<<M_, 256>>>(x, ln_g, ln_b, xnh);
    round_w_kernel<<<4096, 256>>>(Wq, Wkv, Wo, wqkvh, woh);

    // 2) fused Q+KV projection -> fp16 qkv (Q prescaled by 0.125*log2e)
    gemm_h_kernel<true><<<dim3(3072 / GBN, M_ / GBM), 256, GEMM_SMEM>>>(
        xnh, wqkvh, bq, bkv, 1024, nullptr, qkv, 3072, 1024, QSCALE);

    // 3) flash attention (fp16 in/out)
    attn_kernel<<<dim3(S_ / 64, H_, B_), 128, ATTN_SMEM>>>(qkv, kvl, attnh);

    // 4) output projection + bias + residual (fp32 out)
    gemm_h_kernel<false><<<dim3(1024 / GBN, M_ / GBM), 256, GEMM_SMEM>>>(
        attnh, woh, bo, bo, 1 << 30, x, out, 1024, 0, 1.0f);
}